// round 2
// baseline (speedup 1.0000x reference)
#include <cuda_runtime.h>
#include <math.h>

// Problem constants
#define BB 8
#define TT 2048
#define DD 1024
#define WW 16
#define HH 8
#define HDIM 128
#define NWIN (TT / WW)          // 128
#define MTOK (BB * TT)          // 16384
#define D4 (4 * DD)             // 4096
#define D3 (3 * DD)             // 3072

// ---------------------------------------------------------------------------
// Scratch (allocation-free: __device__ globals)
// ---------------------------------------------------------------------------
__device__ float g_x[MTOK * DD];        // x = frame_features + PE
__device__ float g_qkv[MTOK * D3];      // QKV projection
__device__ float g_ao[MTOK * DD];       // attention output (pre out-proj)
__device__ float g_proj[MTOK * DD];     // out-proj result
__device__ float g_h[MTOK * DD];        // after LN1
__device__ float g_f1[MTOK * D4];       // gelu(h @ w1^T + b1)
__device__ float g_f2[MTOK * DD];       // f1 @ w2^T + b2

// ---------------------------------------------------------------------------
// 1) x = frame_features + sinusoidal PE(frame_indices)
//    frame_indices is int32 on disk (JAX silently downcasts int64 without
//    x64 mode). Runtime probe tolerates a genuine little-endian int64 buffer
//    too: int64 arange viewed as i32 is [0,0,1,0,2,0,...] -> i32[1]==0.
// ---------------------------------------------------------------------------
__global__ void pe_add_kernel(const float* __restrict__ ff,
                              const int* __restrict__ idx32,
                              float* __restrict__ x) {
    int i = blockIdx.x * blockDim.x + threadIdx.x;   // over MTOK*DD
    int tok = i >> 10;
    int d = i & (DD - 1);
    bool is64 = (idx32[1] == 0);
    float pos = (float)(is64 ? idx32[2 * tok] : idx32[tok]);
    int k = d & ~1;                                   // even index 0,2,...,1022
    float ang = pos * expf(-9.210340371976184f * (float)k / (float)DD);
    float pe = (d & 1) ? cosf(ang) : sinf(ang);
    x[i] = ff[i] + pe;
}

// ---------------------------------------------------------------------------
// 2) Generic GEMM: C[m][n] = sum_k A[m][k] * W[n][k] + bias[n]  (opt. GELU)
//    A row-major [M,K], W row-major [N,K]. 128x128 block, BK=8, 256 threads,
//    8x8 per thread (split 4+4 for conflict-free LDS.128).
// ---------------------------------------------------------------------------
__device__ __forceinline__ float gelu_exact(float v) {
    return v * 0.5f * (1.0f + erff(v * 0.7071067811865476f));
}

template <int DO_GELU>
__global__ __launch_bounds__(256, 2)
void gemm_nt(const float* __restrict__ A, const float* __restrict__ W,
             const float* __restrict__ bias, float* __restrict__ C,
             int N, int K) {
    __shared__ float As[8][128];
    __shared__ float Ws[8][128];

    const int bm = blockIdx.y * 128;
    const int bn = blockIdx.x * 128;
    const int tid = threadIdx.x;
    const int tx = tid & 15;
    const int ty = tid >> 4;
    const int lr = tid >> 1;          // 0..127
    const int lc = (tid & 1) << 2;    // 0 or 4

    const float* Ag = A + (long)(bm + lr) * K + lc;
    const float* Wg = W + (long)(bn + lr) * K + lc;

    float acc[8][8];
#pragma unroll
    for (int i = 0; i < 8; i++)
#pragma unroll
        for (int j = 0; j < 8; j++) acc[i][j] = 0.0f;

    for (int k0 = 0; k0 < K; k0 += 8) {
        float4 av = *(const float4*)(Ag + k0);
        float4 wv = *(const float4*)(Wg + k0);
        __syncthreads();   // previous iteration's reads complete
        As[lc + 0][lr] = av.x; As[lc + 1][lr] = av.y;
        As[lc + 2][lr] = av.z; As[lc + 3][lr] = av.w;
        Ws[lc + 0][lr] = wv.x; Ws[lc + 1][lr] = wv.y;
        Ws[lc + 2][lr] = wv.z; Ws[lc + 3][lr] = wv.w;
        __syncthreads();
#pragma unroll
        for (int kk = 0; kk < 8; kk++) {
            float4 a0 = *(const float4*)&As[kk][ty << 2];
            float4 a1 = *(const float4*)&As[kk][64 + (ty << 2)];
            float4 w0 = *(const float4*)&Ws[kk][tx << 2];
            float4 w1 = *(const float4*)&Ws[kk][64 + (tx << 2)];
            float a[8] = {a0.x, a0.y, a0.z, a0.w, a1.x, a1.y, a1.z, a1.w};
            float b[8] = {w0.x, w0.y, w0.z, w0.w, w1.x, w1.y, w1.z, w1.w};
#pragma unroll
            for (int i = 0; i < 8; i++)
#pragma unroll
                for (int j = 0; j < 8; j++) acc[i][j] += a[i] * b[j];
        }
    }

#pragma unroll
    for (int i = 0; i < 8; i++) {
        int row = bm + (ty << 2) + ((i & 4) << 4) + (i & 3);
#pragma unroll
        for (int half = 0; half < 2; half++) {
            int cb = bn + (tx << 2) + half * 64;
            float4 o;
            float v0 = acc[i][half * 4 + 0] + bias[cb + 0];
            float v1 = acc[i][half * 4 + 1] + bias[cb + 1];
            float v2 = acc[i][half * 4 + 2] + bias[cb + 2];
            float v3 = acc[i][half * 4 + 3] + bias[cb + 3];
            if (DO_GELU) { v0 = gelu_exact(v0); v1 = gelu_exact(v1);
                           v2 = gelu_exact(v2); v3 = gelu_exact(v3); }
            o.x = v0; o.y = v1; o.z = v2; o.w = v3;
            *(float4*)&C[(long)row * N + cb] = o;
        }
    }
}

// ---------------------------------------------------------------------------
// 3) Per-window attention. One block per (head, window, batch). 256 threads.
// ---------------------------------------------------------------------------
__global__ __launch_bounds__(256)
void attn_win_kernel(const float* __restrict__ qkv, float* __restrict__ o) {
    __shared__ float q[16][132];
    __shared__ float k[16][132];
    __shared__ float v[16][132];
    __shared__ float s[16][16];

    const int h = blockIdx.x;
    const int n = blockIdx.y;
    const int b = blockIdx.z;
    const int tid = threadIdx.x;

    const long base = ((long)b * TT + (long)n * WW) * D3;
    const int qo = h * HDIM;
    const int ko = DD + h * HDIM;
    const int vo = 2 * DD + h * HDIM;

#pragma unroll
    for (int i = 0; i < 8; i++) {
        int e = tid + i * 256;
        int r = e >> 7;
        int d = e & 127;
        long rb = base + (long)r * D3;
        q[r][d] = qkv[rb + qo + d];
        k[r][d] = qkv[rb + ko + d];
        v[r][d] = qkv[rb + vo + d];
    }
    __syncthreads();

    // scores: one thread per (qi, ki)
    {
        int qi = tid >> 4, ki = tid & 15;
        float acc = 0.0f;
#pragma unroll
        for (int d4 = 0; d4 < 32; d4++) {
            float4 qq = *(const float4*)&q[qi][d4 * 4];
            float4 kk = *(const float4*)&k[ki][d4 * 4];
            acc += qq.x * kk.x + qq.y * kk.y + qq.z * kk.z + qq.w * kk.w;
        }
        s[qi][ki] = acc * 0.08838834764831845f;   // 1/sqrt(128)
    }
    __syncthreads();

    // softmax over ki (16 rows, one thread each)
    if (tid < 16) {
        float mx = -1e30f;
#pragma unroll
        for (int j = 0; j < 16; j++) mx = fmaxf(mx, s[tid][j]);
        float p[16];
        float sum = 0.0f;
#pragma unroll
        for (int j = 0; j < 16; j++) { p[j] = expf(s[tid][j] - mx); sum += p[j]; }
        float inv = 1.0f / sum;
#pragma unroll
        for (int j = 0; j < 16; j++) s[tid][j] = p[j] * inv;
    }
    __syncthreads();

    // O = attn @ V
    const long obase = ((long)b * TT + (long)n * WW) * DD + h * HDIM;
#pragma unroll
    for (int i = 0; i < 8; i++) {
        int e = tid + i * 256;
        int r = e >> 7;
        int d = e & 127;
        float acc = 0.0f;
#pragma unroll
        for (int j = 0; j < 16; j++) acc += s[r][j] * v[j][d];
        o[obase + (long)r * DD + d] = acc;
    }
}

// ---------------------------------------------------------------------------
// 4) LayerNorm(a + b) with gain/bias. One block (256 threads) per row of 1024.
// ---------------------------------------------------------------------------
__device__ __forceinline__ float warp_sum(float x) {
#pragma unroll
    for (int off = 16; off > 0; off >>= 1) x += __shfl_xor_sync(0xffffffffu, x, off);
    return x;
}

__global__ __launch_bounds__(256)
void ln_add_kernel(const float* __restrict__ a, const float* __restrict__ bres,
                   const float* __restrict__ g, const float* __restrict__ beta,
                   float* __restrict__ out) {
    __shared__ float rs[8], rq[8], tot[2];
    const int row = blockIdx.x;
    const int tid = threadIdx.x;
    const long rb = (long)row * DD;

    float vals[4];
    float s = 0.0f, sq = 0.0f;
#pragma unroll
    for (int i = 0; i < 4; i++) {
        int c = tid + i * 256;
        float x = a[rb + c] + bres[rb + c];
        vals[i] = x;
        s += x;
        sq += x * x;
    }
    float ws = warp_sum(s), wq = warp_sum(sq);
    int wid = tid >> 5, lane = tid & 31;
    if (lane == 0) { rs[wid] = ws; rq[wid] = wq; }
    __syncthreads();
    if (tid == 0) {
        float ta = 0.0f, tb = 0.0f;
#pragma unroll
        for (int i = 0; i < 8; i++) { ta += rs[i]; tb += rq[i]; }
        tot[0] = ta; tot[1] = tb;
    }
    __syncthreads();
    float mean = tot[0] * (1.0f / DD);
    float var = tot[1] * (1.0f / DD) - mean * mean;
    float inv = rsqrtf(var + 1e-5f);
#pragma unroll
    for (int i = 0; i < 4; i++) {
        int c = tid + i * 256;
        out[rb + c] = (vals[i] - mean) * inv * g[c] + beta[c];
    }
}

// ---------------------------------------------------------------------------
// Launch
// ---------------------------------------------------------------------------
extern "C" void kernel_launch(void* const* d_in, const int* in_sizes, int n_in,
                              void* d_out, int out_size) {
    const float* ff        = (const float*)d_in[0];
    const int*   fi        = (const int*)d_in[1];   // int32 (JAX downcasts int64)
    const float* w_qkv     = (const float*)d_in[2];
    const float* b_qkv     = (const float*)d_in[3];
    const float* w_out     = (const float*)d_in[4];
    const float* b_out     = (const float*)d_in[5];
    const float* w1        = (const float*)d_in[6];
    const float* b1        = (const float*)d_in[7];
    const float* w2        = (const float*)d_in[8];
    const float* b2        = (const float*)d_in[9];
    const float* g1        = (const float*)d_in[10];
    const float* beta1     = (const float*)d_in[11];
    const float* g2        = (const float*)d_in[12];
    const float* beta2     = (const float*)d_in[13];
    float* out             = (float*)d_out;

    float *px, *pqkv, *pao, *pproj, *ph, *pf1, *pf2;
    cudaGetSymbolAddress((void**)&px,    g_x);
    cudaGetSymbolAddress((void**)&pqkv,  g_qkv);
    cudaGetSymbolAddress((void**)&pao,   g_ao);
    cudaGetSymbolAddress((void**)&pproj, g_proj);
    cudaGetSymbolAddress((void**)&ph,    g_h);
    cudaGetSymbolAddress((void**)&pf1,   g_f1);
    cudaGetSymbolAddress((void**)&pf2,   g_f2);

    // 1) positional encoding add
    pe_add_kernel<<<(MTOK * DD) / 256, 256>>>(ff, fi, px);

    // 2) QKV projection: [16384,1024] x [3072,1024]^T
    gemm_nt<0><<<dim3(D3 / 128, MTOK / 128), 256>>>(px, w_qkv, b_qkv, pqkv, D3, DD);

    // 3) windowed attention
    attn_win_kernel<<<dim3(HH, NWIN, BB), 256>>>(pqkv, pao);

    // 4) out projection
    gemm_nt<0><<<dim3(DD / 128, MTOK / 128), 256>>>(pao, w_out, b_out, pproj, DD, DD);

    // 5) LN1(x + proj)
    ln_add_kernel<<<MTOK, 256>>>(px, pproj, g1, beta1, ph);

    // 6) FFN layer 1 with fused GELU: [16384,1024] x [4096,1024]^T
    gemm_nt<1><<<dim3(D4 / 128, MTOK / 128), 256>>>(ph, w1, b1, pf1, D4, DD);

    // 7) FFN layer 2: [16384,4096] x [1024,4096]^T
    gemm_nt<0><<<dim3(DD / 128, MTOK / 128), 256>>>(pf1, w2, b2, pf2, DD, D4);

    // 8) LN2(h + ffn) -> final output
    ln_add_kernel<<<MTOK, 256>>>(ph, pf2, g2, beta2, out);
}

// round 9
// speedup vs baseline: 2.1234x; 2.1234x over previous
#include <cuda_runtime.h>
#include <cuda_bf16.h>
#include <stdint.h>
#include <math.h>

// Problem constants
#define BB 8
#define TT 2048
#define DD 1024
#define WW 16
#define HH 8
#define HDIM 128
#define NWIN (TT / WW)
#define MTOK (BB * TT)          // 16384
#define D4 (4 * DD)             // 4096
#define D3 (3 * DD)             // 3072

// GEMM tiling
#define BM 128
#define BN 128
#define BK 32
#define RSB 80                  // smem row stride bytes (32 bf16 -> 64B, padded to 80)
#define REG_A 0                 // Ahi
#define REG_AL 10240            // Alo  (128 rows * 80B)
#define REG_B 20480             // Bhi
#define REG_BL 30720            // Blo
#define SBUF 40960              // one pipeline buffer
#define GSMEM_BYTES (2 * SBUF)  // 81920

// ---------------------------------------------------------------------------
// Scratch (__device__ globals; allocation-free)
// ---------------------------------------------------------------------------
__device__ float g_x[MTOK * DD];
__device__ __nv_bfloat16 g_xhi[MTOK * DD], g_xlo[MTOK * DD];
__device__ float g_qkv[MTOK * D3];
__device__ __nv_bfloat16 g_aohi[MTOK * DD], g_aolo[MTOK * DD];
__device__ float g_proj[MTOK * DD];
__device__ float g_h[MTOK * DD];
__device__ __nv_bfloat16 g_hhi[MTOK * DD], g_hlo[MTOK * DD];
__device__ __nv_bfloat16 g_f1hi[MTOK * D4], g_f1lo[MTOK * D4];
__device__ float g_f2[MTOK * DD];
__device__ __nv_bfloat16 g_wqkvhi[D3 * DD], g_wqkvlo[D3 * DD];
__device__ __nv_bfloat16 g_wouthi[DD * DD], g_woutlo[DD * DD];
__device__ __nv_bfloat16 g_w1hi[D4 * DD], g_w1lo[D4 * DD];
__device__ __nv_bfloat16 g_w2hi[DD * D4], g_w2lo[DD * D4];

// ---------------------------------------------------------------------------
// Helpers
// ---------------------------------------------------------------------------
__device__ __forceinline__ uint32_t smem_u32(const void* p) {
    uint32_t a;
    asm("{ .reg .u64 t; cvta.to.shared.u64 t, %1; cvt.u32.u64 %0, t; }"
        : "=r"(a) : "l"(p));
    return a;
}
#define CP_ASYNC16(dst, src) \
    asm volatile("cp.async.cg.shared.global [%0], [%1], 16;" :: "r"(dst), "l"(src))
#define CP_COMMIT() asm volatile("cp.async.commit_group;" ::: "memory")
#define CP_WAIT1() asm volatile("cp.async.wait_group 1;" ::: "memory")
#define CP_WAIT0() asm volatile("cp.async.wait_group 0;" ::: "memory")
#define LDSM4(r0, r1, r2, r3, addr) \
    asm volatile("ldmatrix.sync.aligned.m8n8.x4.shared.b16 {%0,%1,%2,%3}, [%4];" \
                 : "=r"(r0), "=r"(r1), "=r"(r2), "=r"(r3) : "r"(addr))
#define MMA16816(d, a, b0, b1) \
    asm volatile("mma.sync.aligned.m16n8k16.row.col.f32.bf16.bf16.f32 " \
                 "{%0,%1,%2,%3},{%4,%5,%6,%7},{%8,%9},{%0,%1,%2,%3};" \
                 : "+f"((d)[0]), "+f"((d)[1]), "+f"((d)[2]), "+f"((d)[3]) \
                 : "r"((a)[0]), "r"((a)[1]), "r"((a)[2]), "r"((a)[3]), \
                   "r"(b0), "r"(b1))

__device__ __forceinline__ void split32(float v, __nv_bfloat16& hi, __nv_bfloat16& lo) {
    hi = __float2bfloat16(v);
    lo = __float2bfloat16(v - __bfloat162float(hi));
}
__device__ __forceinline__ float gelu_exact(float v) {
    return v * 0.5f * (1.0f + erff(v * 0.7071067811865476f));
}

// ---------------------------------------------------------------------------
// bf16x3 GEMM via mma.sync: C[m][n] = sum_k A[m][k]*B[n][k] + bias[n]
// A,B given as bf16 hi/lo pairs (K-major). fp32 accumulate.
// mode 0: fp32 C out. mode 1: GELU then bf16 hi/lo out.
// ---------------------------------------------------------------------------
__global__ __launch_bounds__(256, 1)
void gemm_mma(const __nv_bfloat16* __restrict__ Ahi, const __nv_bfloat16* __restrict__ Alo,
              const __nv_bfloat16* __restrict__ Bhi, const __nv_bfloat16* __restrict__ Blo,
              const float* __restrict__ bias, float* __restrict__ Cf,
              __nv_bfloat16* __restrict__ Chi, __nv_bfloat16* __restrict__ Clo,
              int N, int K, int mode) {
    extern __shared__ char smem[];
    const uint32_t sbase = smem_u32(smem);
    const int tid = threadIdx.x;
    const int w = tid >> 5;
    const int lane = tid & 31;
    const int warp_m = (w >> 2) * 64;
    const int warp_n = (w & 3) * 32;
    const int bm = blockIdx.y * BM;
    const int bn = blockIdx.x * BN;

    // cp.async slot for this thread (A: 4 iters, B: 4 iters)
    const int lrow = (tid >> 2) & 127;   // reused per half
    const int lc16 = tid & 3;

    float acc[4][4][4];
#pragma unroll
    for (int i = 0; i < 4; i++)
#pragma unroll
        for (int j = 0; j < 4; j++)
#pragma unroll
            for (int q = 0; q < 4; q++) acc[i][j][q] = 0.0f;

    const int nc = K / BK;

    // ---- chunk loader ----
    auto load_chunk = [&](int c, int buf) {
        const int k0 = c * BK;
        const uint32_t db = sbase + buf * SBUF;
#pragma unroll
        for (int half = 0; half < 2; half++) {
            // A rows 0..127 in two waves of 64 rows (tid covers 64 rows x 4 cols)
#pragma unroll
            for (int wv = 0; wv < 2; wv++) {
                int row = (wv << 6) + (tid >> 2);
                const __nv_bfloat16* src = (half ? Alo : Ahi) +
                    (size_t)(bm + row) * K + k0 + lc16 * 8;
                uint32_t dst = db + (half ? REG_AL : REG_A) + row * RSB + lc16 * 16;
                CP_ASYNC16(dst, src);
            }
#pragma unroll
            for (int wv = 0; wv < 2; wv++) {
                int row = (wv << 6) + (tid >> 2);
                const __nv_bfloat16* src = (half ? Blo : Bhi) +
                    (size_t)(bn + row) * K + k0 + lc16 * 8;
                uint32_t dst = db + (half ? REG_BL : REG_B) + row * RSB + lc16 * 16;
                CP_ASYNC16(dst, src);
            }
        }
    };

    load_chunk(0, 0);
    CP_COMMIT();

    const int j8 = lane >> 3;       // ldmatrix sub-matrix index
    const int l7 = lane & 7;

    for (int c = 0; c < nc; c++) {
        const int buf = c & 1;
        if (c + 1 < nc) {
            load_chunk(c + 1, buf ^ 1);
            CP_COMMIT();
            CP_WAIT1();
        } else {
            CP_WAIT0();
        }
        __syncthreads();

        const uint32_t db = sbase + buf * SBUF;
#pragma unroll
        for (int ks = 0; ks < 2; ks++) {
            // --- B fragments (hi and lo resident) ---
            uint32_t bh[4][2], bl[4][2];
#pragma unroll
            for (int p = 0; p < 2; p++) {
                int brow = warp_n + p * 16 + ((j8 >> 1) << 3) + l7;
                int bc16 = ks * 2 + (j8 & 1);
                uint32_t ab = db + REG_B + brow * RSB + bc16 * 16;
                LDSM4(bh[p * 2][0], bh[p * 2][1], bh[p * 2 + 1][0], bh[p * 2 + 1][1], ab);
                uint32_t abl = db + REG_BL + brow * RSB + bc16 * 16;
                LDSM4(bl[p * 2][0], bl[p * 2][1], bl[p * 2 + 1][0], bl[p * 2 + 1][1], abl);
            }
            // --- A hi fragments; do hi*hi and hi*lo ---
            {
                uint32_t af[4][4];
#pragma unroll
                for (int mt = 0; mt < 4; mt++) {
                    int arow = warp_m + mt * 16 + ((j8 & 1) << 3) + l7;
                    int ac16 = ks * 2 + (j8 >> 1);
                    uint32_t aa = db + REG_A + arow * RSB + ac16 * 16;
                    LDSM4(af[mt][0], af[mt][1], af[mt][2], af[mt][3], aa);
                }
#pragma unroll
                for (int mt = 0; mt < 4; mt++)
#pragma unroll
                    for (int nt = 0; nt < 4; nt++) {
                        MMA16816(acc[mt][nt], af[mt], bh[nt][0], bh[nt][1]);
                        MMA16816(acc[mt][nt], af[mt], bl[nt][0], bl[nt][1]);
                    }
            }
            // --- A lo fragments; do lo*hi ---
            {
                uint32_t af[4][4];
#pragma unroll
                for (int mt = 0; mt < 4; mt++) {
                    int arow = warp_m + mt * 16 + ((j8 & 1) << 3) + l7;
                    int ac16 = ks * 2 + (j8 >> 1);
                    uint32_t aa = db + REG_AL + arow * RSB + ac16 * 16;
                    LDSM4(af[mt][0], af[mt][1], af[mt][2], af[mt][3], aa);
                }
#pragma unroll
                for (int mt = 0; mt < 4; mt++)
#pragma unroll
                    for (int nt = 0; nt < 4; nt++)
                        MMA16816(acc[mt][nt], af[mt], bh[nt][0], bh[nt][1]);
            }
        }
        __syncthreads();
    }

    // ---- epilogue ----
    const int g4 = lane >> 2;
    const int q2 = (lane & 3) * 2;
#pragma unroll
    for (int mt = 0; mt < 4; mt++) {
#pragma unroll
        for (int half = 0; half < 2; half++) {
            int row = bm + warp_m + mt * 16 + g4 + half * 8;
#pragma unroll
            for (int nt = 0; nt < 4; nt++) {
                int col = bn + warp_n + nt * 8 + q2;
                float v0 = acc[mt][nt][half * 2 + 0] + __ldg(&bias[col + 0]);
                float v1 = acc[mt][nt][half * 2 + 1] + __ldg(&bias[col + 1]);
                if (mode == 0) {
                    float2 o; o.x = v0; o.y = v1;
                    *(float2*)&Cf[(size_t)row * N + col] = o;
                } else {
                    v0 = gelu_exact(v0);
                    v1 = gelu_exact(v1);
                    __nv_bfloat16 h0, l0, h1, l1;
                    split32(v0, h0, l0);
                    split32(v1, h1, l1);
                    __nv_bfloat162 ph; ph.x = h0; ph.y = h1;
                    __nv_bfloat162 pl; pl.x = l0; pl.y = l1;
                    *(__nv_bfloat162*)&Chi[(size_t)row * N + col] = ph;
                    *(__nv_bfloat162*)&Clo[(size_t)row * N + col] = pl;
                }
            }
        }
    }
}

// ---------------------------------------------------------------------------
// PE add: x = ff + PE, plus bf16 hi/lo split of x
// ---------------------------------------------------------------------------
__global__ void pe_add_kernel(const float* __restrict__ ff,
                              const int* __restrict__ idx32,
                              float* __restrict__ x,
                              __nv_bfloat16* __restrict__ xhi,
                              __nv_bfloat16* __restrict__ xlo) {
    int i = blockIdx.x * blockDim.x + threadIdx.x;
    int tok = i >> 10;
    int d = i & (DD - 1);
    bool is64 = (idx32[1] == 0);
    float pos = (float)(is64 ? idx32[2 * tok] : idx32[tok]);
    int k = d & ~1;
    float ang = pos * expf(-9.210340371976184f * (float)k / (float)DD);
    float pe = (d & 1) ? cosf(ang) : sinf(ang);
    float v = ff[i] + pe;
    x[i] = v;
    __nv_bfloat16 hi, lo;
    split32(v, hi, lo);
    xhi[i] = hi; xlo[i] = lo;
}

// ---------------------------------------------------------------------------
// Weight split
// ---------------------------------------------------------------------------
__global__ void split_kernel(const float* __restrict__ in,
                             __nv_bfloat16* __restrict__ hi,
                             __nv_bfloat16* __restrict__ lo, int n) {
    int i = blockIdx.x * blockDim.x + threadIdx.x;
    if (i < n) {
        __nv_bfloat16 h, l;
        split32(in[i], h, l);
        hi[i] = h; lo[i] = l;
    }
}

// ---------------------------------------------------------------------------
// Per-window attention (fp32), emits bf16 hi/lo of attention output
// ---------------------------------------------------------------------------
__global__ __launch_bounds__(256)
void attn_win_kernel(const float* __restrict__ qkv,
                     __nv_bfloat16* __restrict__ ohi,
                     __nv_bfloat16* __restrict__ olo) {
    __shared__ float q[16][132];
    __shared__ float k[16][132];
    __shared__ float v[16][132];
    __shared__ float s[16][16];

    const int h = blockIdx.x;
    const int n = blockIdx.y;
    const int b = blockIdx.z;
    const int tid = threadIdx.x;

    const long base = ((long)b * TT + (long)n * WW) * D3;
    const int qo = h * HDIM;
    const int ko = DD + h * HDIM;
    const int vo = 2 * DD + h * HDIM;

#pragma unroll
    for (int i = 0; i < 8; i++) {
        int e = tid + i * 256;
        int r = e >> 7;
        int d = e & 127;
        long rb = base + (long)r * D3;
        q[r][d] = qkv[rb + qo + d];
        k[r][d] = qkv[rb + ko + d];
        v[r][d] = qkv[rb + vo + d];
    }
    __syncthreads();

    {
        int qi = tid >> 4, ki = tid & 15;
        float acc = 0.0f;
#pragma unroll
        for (int d4 = 0; d4 < 32; d4++) {
            float4 qq = *(const float4*)&q[qi][d4 * 4];
            float4 kk = *(const float4*)&k[ki][d4 * 4];
            acc += qq.x * kk.x + qq.y * kk.y + qq.z * kk.z + qq.w * kk.w;
        }
        s[qi][ki] = acc * 0.08838834764831845f;
    }
    __syncthreads();

    if (tid < 16) {
        float mx = -1e30f;
#pragma unroll
        for (int j = 0; j < 16; j++) mx = fmaxf(mx, s[tid][j]);
        float p[16];
        float sum = 0.0f;
#pragma unroll
        for (int j = 0; j < 16; j++) { p[j] = expf(s[tid][j] - mx); sum += p[j]; }
        float inv = 1.0f / sum;
#pragma unroll
        for (int j = 0; j < 16; j++) s[tid][j] = p[j] * inv;
    }
    __syncthreads();

    const long obase = ((long)b * TT + (long)n * WW) * DD + h * HDIM;
#pragma unroll
    for (int i = 0; i < 8; i++) {
        int e = tid + i * 256;
        int r = e >> 7;
        int d = e & 127;
        float acc = 0.0f;
#pragma unroll
        for (int j = 0; j < 16; j++) acc += s[r][j] * v[j][d];
        __nv_bfloat16 hi, lo;
        split32(acc, hi, lo);
        long oi = obase + (long)r * DD + d;
        ohi[oi] = hi; olo[oi] = lo;
    }
}

// ---------------------------------------------------------------------------
// LayerNorm(a + b); optionally emits bf16 hi/lo of the result
// ---------------------------------------------------------------------------
__device__ __forceinline__ float warp_sum(float x) {
#pragma unroll
    for (int off = 16; off > 0; off >>= 1) x += __shfl_xor_sync(0xffffffffu, x, off);
    return x;
}

__global__ __launch_bounds__(256)
void ln_add_kernel(const float* __restrict__ a, const float* __restrict__ bres,
                   const float* __restrict__ g, const float* __restrict__ beta,
                   float* __restrict__ out,
                   __nv_bfloat16* __restrict__ ohi, __nv_bfloat16* __restrict__ olo) {
    __shared__ float rs[8], rq[8], tot[2];
    const int row = blockIdx.x;
    const int tid = threadIdx.x;
    const long rb = (long)row * DD;

    float vals[4];
    float s = 0.0f, sq = 0.0f;
#pragma unroll
    for (int i = 0; i < 4; i++) {
        int c = tid + i * 256;
        float x = a[rb + c] + bres[rb + c];
        vals[i] = x;
        s += x;
        sq += x * x;
    }
    float ws = warp_sum(s), wq = warp_sum(sq);
    int wid = tid >> 5, lane = tid & 31;
    if (lane == 0) { rs[wid] = ws; rq[wid] = wq; }
    __syncthreads();
    if (tid == 0) {
        float ta = 0.0f, tb = 0.0f;
#pragma unroll
        for (int i = 0; i < 8; i++) { ta += rs[i]; tb += rq[i]; }
        tot[0] = ta; tot[1] = tb;
    }
    __syncthreads();
    float mean = tot[0] * (1.0f / DD);
    float var = tot[1] * (1.0f / DD) - mean * mean;
    float inv = rsqrtf(var + 1e-5f);
#pragma unroll
    for (int i = 0; i < 4; i++) {
        int c = tid + i * 256;
        float o = (vals[i] - mean) * inv * g[c] + beta[c];
        out[rb + c] = o;
        if (ohi) {
            __nv_bfloat16 hi, lo;
            split32(o, hi, lo);
            ohi[rb + c] = hi; olo[rb + c] = lo;
        }
    }
}

// ---------------------------------------------------------------------------
// Launch
// ---------------------------------------------------------------------------
extern "C" void kernel_launch(void* const* d_in, const int* in_sizes, int n_in,
                              void* d_out, int out_size) {
    const float* ff    = (const float*)d_in[0];
    const int*   fi    = (const int*)d_in[1];
    const float* w_qkv = (const float*)d_in[2];
    const float* b_qkv = (const float*)d_in[3];
    const float* w_out = (const float*)d_in[4];
    const float* b_out = (const float*)d_in[5];
    const float* w1    = (const float*)d_in[6];
    const float* b1    = (const float*)d_in[7];
    const float* w2    = (const float*)d_in[8];
    const float* b2    = (const float*)d_in[9];
    const float* g1    = (const float*)d_in[10];
    const float* bet1  = (const float*)d_in[11];
    const float* g2    = (const float*)d_in[12];
    const float* bet2  = (const float*)d_in[13];
    float* out         = (float*)d_out;

    float *px, *pqkv, *pproj, *ph, *pf2;
    __nv_bfloat16 *pxhi, *pxlo, *paohi, *paolo, *phhi, *phlo, *pf1hi, *pf1lo;
    __nv_bfloat16 *pwqkvhi, *pwqkvlo, *pwouthi, *pwoutlo, *pw1hi, *pw1lo, *pw2hi, *pw2lo;
    cudaGetSymbolAddress((void**)&px, g_x);
    cudaGetSymbolAddress((void**)&pxhi, g_xhi);
    cudaGetSymbolAddress((void**)&pxlo, g_xlo);
    cudaGetSymbolAddress((void**)&pqkv, g_qkv);
    cudaGetSymbolAddress((void**)&paohi, g_aohi);
    cudaGetSymbolAddress((void**)&paolo, g_aolo);
    cudaGetSymbolAddress((void**)&pproj, g_proj);
    cudaGetSymbolAddress((void**)&ph, g_h);
    cudaGetSymbolAddress((void**)&phhi, g_hhi);
    cudaGetSymbolAddress((void**)&phlo, g_hlo);
    cudaGetSymbolAddress((void**)&pf1hi, g_f1hi);
    cudaGetSymbolAddress((void**)&pf1lo, g_f1lo);
    cudaGetSymbolAddress((void**)&pf2, g_f2);
    cudaGetSymbolAddress((void**)&pwqkvhi, g_wqkvhi);
    cudaGetSymbolAddress((void**)&pwqkvlo, g_wqkvlo);
    cudaGetSymbolAddress((void**)&pwouthi, g_wouthi);
    cudaGetSymbolAddress((void**)&pwoutlo, g_woutlo);
    cudaGetSymbolAddress((void**)&pw1hi, g_w1hi);
    cudaGetSymbolAddress((void**)&pw1lo, g_w1lo);
    cudaGetSymbolAddress((void**)&pw2hi, g_w2hi);
    cudaGetSymbolAddress((void**)&pw2lo, g_w2lo);

    cudaFuncSetAttribute(gemm_mma, cudaFuncAttributeMaxDynamicSharedMemorySize, GSMEM_BYTES);

    // weight splits
    split_kernel<<<(D3 * DD) / 256, 256>>>(w_qkv, pwqkvhi, pwqkvlo, D3 * DD);
    split_kernel<<<(DD * DD) / 256, 256>>>(w_out, pwouthi, pwoutlo, DD * DD);
    split_kernel<<<(D4 * DD) / 256, 256>>>(w1, pw1hi, pw1lo, D4 * DD);
    split_kernel<<<(DD * D4) / 256, 256>>>(w2, pw2hi, pw2lo, DD * D4);

    // 1) PE add + split
    pe_add_kernel<<<(MTOK * DD) / 256, 256>>>(ff, fi, px, pxhi, pxlo);

    // 2) QKV projection (fp32 out for attention)
    gemm_mma<<<dim3(D3 / BN, MTOK / BM), 256, GSMEM_BYTES>>>(
        pxhi, pxlo, pwqkvhi, pwqkvlo, b_qkv, pqkv, nullptr, nullptr, D3, DD, 0);

    // 3) windowed attention -> ao hi/lo
    attn_win_kernel<<<dim3(HH, NWIN, BB), 256>>>(pqkv, paohi, paolo);

    // 4) out projection (fp32 out for residual)
    gemm_mma<<<dim3(DD / BN, MTOK / BM), 256, GSMEM_BYTES>>>(
        paohi, paolo, pwouthi, pwoutlo, b_out, pproj, nullptr, nullptr, DD, DD, 0);

    // 5) LN1(x + proj) -> h fp32 + hi/lo
    ln_add_kernel<<<MTOK, 256>>>(px, pproj, g1, bet1, ph, phhi, phlo);

    // 6) FFN1 + GELU -> f1 hi/lo (bf16 only)
    gemm_mma<<<dim3(D4 / BN, MTOK / BM), 256, GSMEM_BYTES>>>(
        phhi, phlo, pw1hi, pw1lo, b1, nullptr, pf1hi, pf1lo, D4, DD, 1);

    // 7) FFN2 -> f2 fp32
    gemm_mma<<<dim3(DD / BN, MTOK / BM), 256, GSMEM_BYTES>>>(
        pf1hi, pf1lo, pw2hi, pw2lo, b2, pf2, nullptr, nullptr, DD, D4, 0);

    // 8) LN2(h + f2) -> out
    ln_add_kernel<<<MTOK, 256>>>(ph, pf2, g2, bet2, out, nullptr, nullptr);
}

// round 10
// speedup vs baseline: 2.5538x; 1.2027x over previous
#include <cuda_runtime.h>
#include <cuda_bf16.h>
#include <stdint.h>
#include <math.h>

// Problem constants
#define BB 8
#define TT 2048
#define DD 1024
#define WW 16
#define HH 8
#define HDIM 128
#define NWIN (TT / WW)
#define MTOK (BB * TT)          // 16384
#define D4 (4 * DD)             // 4096
#define D3 (3 * DD)             // 3072

// GEMM tiling
#define BM 128
#define BN 128
#define BK 32
#define RSB 80                  // smem row stride bytes (32 bf16 -> 64B, padded to 80)
#define REG_A 0                 // Ahi
#define REG_AL 10240            // Alo  (128 rows * 80B)
#define REG_B 20480             // Bhi
#define REG_BL 30720            // Blo
#define SBUF 40960              // one pipeline buffer
#define GSMEM_BYTES (2 * SBUF)  // 81920 (x2 CTAs/SM = 160KB <= 227KB)

// ---------------------------------------------------------------------------
// Scratch (__device__ globals; allocation-free)
// ---------------------------------------------------------------------------
__device__ float g_x[MTOK * DD];
__device__ __nv_bfloat16 g_xhi[MTOK * DD], g_xlo[MTOK * DD];
__device__ float g_qkv[MTOK * D3];
__device__ __nv_bfloat16 g_aohi[MTOK * DD], g_aolo[MTOK * DD];
__device__ float g_proj[MTOK * DD];
__device__ float g_h[MTOK * DD];
__device__ __nv_bfloat16 g_hhi[MTOK * DD], g_hlo[MTOK * DD];
__device__ __nv_bfloat16 g_f1hi[MTOK * D4], g_f1lo[MTOK * D4];
__device__ float g_f2[MTOK * DD];
__device__ __nv_bfloat16 g_wqkvhi[D3 * DD], g_wqkvlo[D3 * DD];
__device__ __nv_bfloat16 g_wouthi[DD * DD], g_woutlo[DD * DD];
__device__ __nv_bfloat16 g_w1hi[D4 * DD], g_w1lo[D4 * DD];
__device__ __nv_bfloat16 g_w2hi[DD * D4], g_w2lo[DD * D4];

// ---------------------------------------------------------------------------
// Helpers
// ---------------------------------------------------------------------------
__device__ __forceinline__ uint32_t smem_u32(const void* p) {
    uint32_t a;
    asm("{ .reg .u64 t; cvta.to.shared.u64 t, %1; cvt.u32.u64 %0, t; }"
        : "=r"(a) : "l"(p));
    return a;
}
#define CP_ASYNC16(dst, src) \
    asm volatile("cp.async.cg.shared.global [%0], [%1], 16;" :: "r"(dst), "l"(src))
#define CP_COMMIT() asm volatile("cp.async.commit_group;" ::: "memory")
#define CP_WAIT1() asm volatile("cp.async.wait_group 1;" ::: "memory")
#define CP_WAIT0() asm volatile("cp.async.wait_group 0;" ::: "memory")
#define LDSM4(r0, r1, r2, r3, addr) \
    asm volatile("ldmatrix.sync.aligned.m8n8.x4.shared.b16 {%0,%1,%2,%3}, [%4];" \
                 : "=r"(r0), "=r"(r1), "=r"(r2), "=r"(r3) : "r"(addr))
#define MMA16816(d, a, b0, b1) \
    asm volatile("mma.sync.aligned.m16n8k16.row.col.f32.bf16.bf16.f32 " \
                 "{%0,%1,%2,%3},{%4,%5,%6,%7},{%8,%9},{%0,%1,%2,%3};" \
                 : "+f"((d)[0]), "+f"((d)[1]), "+f"((d)[2]), "+f"((d)[3]) \
                 : "r"((a)[0]), "r"((a)[1]), "r"((a)[2]), "r"((a)[3]), \
                   "r"(b0), "r"(b1))

__device__ __forceinline__ void split32(float v, __nv_bfloat16& hi, __nv_bfloat16& lo) {
    hi = __float2bfloat16(v);
    lo = __float2bfloat16(v - __bfloat162float(hi));
}
__device__ __forceinline__ float gelu_exact(float v) {
    return v * 0.5f * (1.0f + erff(v * 0.7071067811865476f));
}

// ---------------------------------------------------------------------------
// bf16x3 GEMM via mma.sync: C[m][n] = sum_k A[m][k]*B[n][k] + bias[n]
// 128x128 CTA tile, 8 warps (64x32 warp tile), BK=32, cp.async double buffer.
// __launch_bounds__(256,2): 2 CTAs/SM so co-resident CTAs hide sync bubbles.
// mode 0: fp32 C out. mode 1: GELU then bf16 hi/lo out.
// ---------------------------------------------------------------------------
__global__ __launch_bounds__(256, 2)
void gemm_mma(const __nv_bfloat16* __restrict__ Ahi, const __nv_bfloat16* __restrict__ Alo,
              const __nv_bfloat16* __restrict__ Bhi, const __nv_bfloat16* __restrict__ Blo,
              const float* __restrict__ bias, float* __restrict__ Cf,
              __nv_bfloat16* __restrict__ Chi, __nv_bfloat16* __restrict__ Clo,
              int N, int K, int mode) {
    extern __shared__ char smem[];
    const uint32_t sbase = smem_u32(smem);
    const int tid = threadIdx.x;
    const int w = tid >> 5;
    const int lane = tid & 31;
    const int warp_m = (w >> 2) * 64;
    const int warp_n = (w & 3) * 32;
    const int bm = blockIdx.y * BM;
    const int bn = blockIdx.x * BN;

    float acc[4][4][4];
#pragma unroll
    for (int i = 0; i < 4; i++)
#pragma unroll
        for (int j = 0; j < 4; j++)
#pragma unroll
            for (int q = 0; q < 4; q++) acc[i][j][q] = 0.0f;

    const int nc = K / BK;

    // per-thread load slots: row tid>>2 (+64), 16B-col tid&3
    const int lr = tid >> 2;
    const int lc16 = tid & 3;
    const __nv_bfloat16* pAh = Ahi + (size_t)(bm + lr) * K + lc16 * 8;
    const __nv_bfloat16* pAl = Alo + (size_t)(bm + lr) * K + lc16 * 8;
    const __nv_bfloat16* pBh = Bhi + (size_t)(bn + lr) * K + lc16 * 8;
    const __nv_bfloat16* pBl = Blo + (size_t)(bn + lr) * K + lc16 * 8;
    const size_t rsk = (size_t)64 * K;
    const uint32_t dsto = lr * RSB + lc16 * 16;

    auto load_chunk = [&](int c, int buf) {
        const uint32_t db = sbase + buf * SBUF + dsto;
        const size_t ko = (size_t)c * BK;
        CP_ASYNC16(db + REG_A, pAh + ko);
        CP_ASYNC16(db + REG_A + 64 * RSB, pAh + rsk + ko);
        CP_ASYNC16(db + REG_AL, pAl + ko);
        CP_ASYNC16(db + REG_AL + 64 * RSB, pAl + rsk + ko);
        CP_ASYNC16(db + REG_B, pBh + ko);
        CP_ASYNC16(db + REG_B + 64 * RSB, pBh + rsk + ko);
        CP_ASYNC16(db + REG_BL, pBl + ko);
        CP_ASYNC16(db + REG_BL + 64 * RSB, pBl + rsk + ko);
    };

    load_chunk(0, 0);
    CP_COMMIT();

    const int j8 = lane >> 3;       // ldmatrix sub-matrix index
    const int l7 = lane & 7;

    for (int c = 0; c < nc; c++) {
        const int buf = c & 1;
        if (c + 1 < nc) {
            load_chunk(c + 1, buf ^ 1);
            CP_COMMIT();
            CP_WAIT1();
        } else {
            CP_WAIT0();
        }
        __syncthreads();

        const uint32_t db = sbase + buf * SBUF;
#pragma unroll
        for (int ks = 0; ks < 2; ks++) {
            // --- B hi fragments ---
            uint32_t bh[4][2];
#pragma unroll
            for (int p = 0; p < 2; p++) {
                int brow = warp_n + p * 16 + ((j8 >> 1) << 3) + l7;
                int bc16 = ks * 2 + (j8 & 1);
                uint32_t ab = db + REG_B + brow * RSB + bc16 * 16;
                LDSM4(bh[p * 2][0], bh[p * 2][1], bh[p * 2 + 1][0], bh[p * 2 + 1][1], ab);
            }
            {
                // --- A hi fragments: hh then hl ---
                uint32_t af[4][4];
#pragma unroll
                for (int mt = 0; mt < 4; mt++) {
                    int arow = warp_m + mt * 16 + ((j8 & 1) << 3) + l7;
                    int ac16 = ks * 2 + (j8 >> 1);
                    uint32_t aa = db + REG_A + arow * RSB + ac16 * 16;
                    LDSM4(af[mt][0], af[mt][1], af[mt][2], af[mt][3], aa);
                }
#pragma unroll
                for (int mt = 0; mt < 4; mt++)
#pragma unroll
                    for (int nt = 0; nt < 4; nt++)
                        MMA16816(acc[mt][nt], af[mt], bh[nt][0], bh[nt][1]);
                // B lo fragments (short lifetime)
                uint32_t bl[4][2];
#pragma unroll
                for (int p = 0; p < 2; p++) {
                    int brow = warp_n + p * 16 + ((j8 >> 1) << 3) + l7;
                    int bc16 = ks * 2 + (j8 & 1);
                    uint32_t abl = db + REG_BL + brow * RSB + bc16 * 16;
                    LDSM4(bl[p * 2][0], bl[p * 2][1], bl[p * 2 + 1][0], bl[p * 2 + 1][1], abl);
                }
#pragma unroll
                for (int mt = 0; mt < 4; mt++)
#pragma unroll
                    for (int nt = 0; nt < 4; nt++)
                        MMA16816(acc[mt][nt], af[mt], bl[nt][0], bl[nt][1]);
                // --- A lo fragments (reuse af): lh ---
#pragma unroll
                for (int mt = 0; mt < 4; mt++) {
                    int arow = warp_m + mt * 16 + ((j8 & 1) << 3) + l7;
                    int ac16 = ks * 2 + (j8 >> 1);
                    uint32_t aa = db + REG_AL + arow * RSB + ac16 * 16;
                    LDSM4(af[mt][0], af[mt][1], af[mt][2], af[mt][3], aa);
                }
#pragma unroll
                for (int mt = 0; mt < 4; mt++)
#pragma unroll
                    for (int nt = 0; nt < 4; nt++)
                        MMA16816(acc[mt][nt], af[mt], bh[nt][0], bh[nt][1]);
            }
        }
        __syncthreads();
    }

    // ---- epilogue ----
    const int g4 = lane >> 2;
    const int q2 = (lane & 3) * 2;
#pragma unroll
    for (int mt = 0; mt < 4; mt++) {
#pragma unroll
        for (int half = 0; half < 2; half++) {
            int row = bm + warp_m + mt * 16 + g4 + half * 8;
#pragma unroll
            for (int nt = 0; nt < 4; nt++) {
                int col = bn + warp_n + nt * 8 + q2;
                float v0 = acc[mt][nt][half * 2 + 0] + __ldg(&bias[col + 0]);
                float v1 = acc[mt][nt][half * 2 + 1] + __ldg(&bias[col + 1]);
                if (mode == 0) {
                    float2 o; o.x = v0; o.y = v1;
                    *(float2*)&Cf[(size_t)row * N + col] = o;
                } else {
                    v0 = gelu_exact(v0);
                    v1 = gelu_exact(v1);
                    __nv_bfloat16 h0, l0, h1, l1;
                    split32(v0, h0, l0);
                    split32(v1, h1, l1);
                    __nv_bfloat162 ph; ph.x = h0; ph.y = h1;
                    __nv_bfloat162 pl; pl.x = l0; pl.y = l1;
                    *(__nv_bfloat162*)&Chi[(size_t)row * N + col] = ph;
                    *(__nv_bfloat162*)&Clo[(size_t)row * N + col] = pl;
                }
            }
        }
    }
}

// ---------------------------------------------------------------------------
// PE add: one thread per (even,odd) pair; one sincosf per pair
// ---------------------------------------------------------------------------
__global__ void pe_add_kernel(const float* __restrict__ ff,
                              const int* __restrict__ idx32,
                              float* __restrict__ x,
                              __nv_bfloat16* __restrict__ xhi,
                              __nv_bfloat16* __restrict__ xlo) {
    int p = blockIdx.x * blockDim.x + threadIdx.x;   // pair index over MTOK*DD/2
    int tok = p >> 9;
    int d = (p & 511) << 1;                           // even d
    bool is64 = (idx32[1] == 0);
    float pos = (float)(is64 ? idx32[2 * tok] : idx32[tok]);
    float ang = pos * expf(-9.210340371976184f * (float)d / (float)DD);
    float s, c;
    sincosf(ang, &s, &c);
    size_t i = (size_t)p * 2;
    float2 f = *(const float2*)&ff[i];
    float v0 = f.x + s;
    float v1 = f.y + c;
    *(float2*)&x[i] = make_float2(v0, v1);
    __nv_bfloat16 h0, l0, h1, l1;
    split32(v0, h0, l0);
    split32(v1, h1, l1);
    __nv_bfloat162 ph; ph.x = h0; ph.y = h1;
    __nv_bfloat162 pl; pl.x = l0; pl.y = l1;
    *(__nv_bfloat162*)&xhi[i] = ph;
    *(__nv_bfloat162*)&xlo[i] = pl;
}

// ---------------------------------------------------------------------------
// Weight split (vectorized: float4 in, 2x bf162 out per stream)
// ---------------------------------------------------------------------------
__global__ void split_kernel(const float* __restrict__ in,
                             __nv_bfloat16* __restrict__ hi,
                             __nv_bfloat16* __restrict__ lo, int n4) {
    int i = blockIdx.x * blockDim.x + threadIdx.x;
    if (i < n4) {
        size_t b = (size_t)i * 4;
        float4 v = *(const float4*)&in[b];
        __nv_bfloat16 h[4], l[4];
        split32(v.x, h[0], l[0]);
        split32(v.y, h[1], l[1]);
        split32(v.z, h[2], l[2]);
        split32(v.w, h[3], l[3]);
        __nv_bfloat162 p0, p1;
        p0.x = h[0]; p0.y = h[1]; p1.x = h[2]; p1.y = h[3];
        *(__nv_bfloat162*)&hi[b] = p0;
        *(__nv_bfloat162*)&hi[b + 2] = p1;
        p0.x = l[0]; p0.y = l[1]; p1.x = l[2]; p1.y = l[3];
        *(__nv_bfloat162*)&lo[b] = p0;
        *(__nv_bfloat162*)&lo[b + 2] = p1;
    }
}

// ---------------------------------------------------------------------------
// Per-window attention (fp32), emits bf16 hi/lo of attention output
// ---------------------------------------------------------------------------
__global__ __launch_bounds__(256)
void attn_win_kernel(const float* __restrict__ qkv,
                     __nv_bfloat16* __restrict__ ohi,
                     __nv_bfloat16* __restrict__ olo) {
    __shared__ float q[16][132];
    __shared__ float k[16][132];
    __shared__ float v[16][132];
    __shared__ float s[16][16];

    const int h = blockIdx.x;
    const int n = blockIdx.y;
    const int b = blockIdx.z;
    const int tid = threadIdx.x;

    const long base = ((long)b * TT + (long)n * WW) * D3;
    const int qo = h * HDIM;
    const int ko = DD + h * HDIM;
    const int vo = 2 * DD + h * HDIM;

#pragma unroll
    for (int i = 0; i < 8; i++) {
        int e = tid + i * 256;
        int r = e >> 7;
        int d = e & 127;
        long rb = base + (long)r * D3;
        q[r][d] = qkv[rb + qo + d];
        k[r][d] = qkv[rb + ko + d];
        v[r][d] = qkv[rb + vo + d];
    }
    __syncthreads();

    {
        int qi = tid >> 4, ki = tid & 15;
        float acc = 0.0f;
#pragma unroll
        for (int d4 = 0; d4 < 32; d4++) {
            float4 qq = *(const float4*)&q[qi][d4 * 4];
            float4 kk = *(const float4*)&k[ki][d4 * 4];
            acc += qq.x * kk.x + qq.y * kk.y + qq.z * kk.z + qq.w * kk.w;
        }
        s[qi][ki] = acc * 0.08838834764831845f;
    }
    __syncthreads();

    if (tid < 16) {
        float mx = -1e30f;
#pragma unroll
        for (int j = 0; j < 16; j++) mx = fmaxf(mx, s[tid][j]);
        float p[16];
        float sum = 0.0f;
#pragma unroll
        for (int j = 0; j < 16; j++) { p[j] = expf(s[tid][j] - mx); sum += p[j]; }
        float inv = 1.0f / sum;
#pragma unroll
        for (int j = 0; j < 16; j++) s[tid][j] = p[j] * inv;
    }
    __syncthreads();

    const long obase = ((long)b * TT + (long)n * WW) * DD + h * HDIM;
#pragma unroll
    for (int i = 0; i < 8; i++) {
        int e = tid + i * 256;
        int r = e >> 7;
        int d = e & 127;
        float acc = 0.0f;
#pragma unroll
        for (int j = 0; j < 16; j++) acc += s[r][j] * v[j][d];
        __nv_bfloat16 hi, lo;
        split32(acc, hi, lo);
        long oi = obase + (long)r * DD + d;
        ohi[oi] = hi; olo[oi] = lo;
    }
}

// ---------------------------------------------------------------------------
// LayerNorm(a + b); optionally emits bf16 hi/lo of the result
// ---------------------------------------------------------------------------
__device__ __forceinline__ float warp_sum(float x) {
#pragma unroll
    for (int off = 16; off > 0; off >>= 1) x += __shfl_xor_sync(0xffffffffu, x, off);
    return x;
}

__global__ __launch_bounds__(256)
void ln_add_kernel(const float* __restrict__ a, const float* __restrict__ bres,
                   const float* __restrict__ g, const float* __restrict__ beta,
                   float* __restrict__ out,
                   __nv_bfloat16* __restrict__ ohi, __nv_bfloat16* __restrict__ olo) {
    __shared__ float rs[8], rq[8], tot[2];
    const int row = blockIdx.x;
    const int tid = threadIdx.x;
    const long rb = (long)row * DD;

    float vals[4];
    float s = 0.0f, sq = 0.0f;
#pragma unroll
    for (int i = 0; i < 4; i++) {
        int c = tid + i * 256;
        float x = a[rb + c] + bres[rb + c];
        vals[i] = x;
        s += x;
        sq += x * x;
    }
    float ws = warp_sum(s), wq = warp_sum(sq);
    int wid = tid >> 5, lane = tid & 31;
    if (lane == 0) { rs[wid] = ws; rq[wid] = wq; }
    __syncthreads();
    if (tid == 0) {
        float ta = 0.0f, tb = 0.0f;
#pragma unroll
        for (int i = 0; i < 8; i++) { ta += rs[i]; tb += rq[i]; }
        tot[0] = ta; tot[1] = tb;
    }
    __syncthreads();
    float mean = tot[0] * (1.0f / DD);
    float var = tot[1] * (1.0f / DD) - mean * mean;
    float inv = rsqrtf(var + 1e-5f);
#pragma unroll
    for (int i = 0; i < 4; i++) {
        int c = tid + i * 256;
        float o = (vals[i] - mean) * inv * g[c] + beta[c];
        out[rb + c] = o;
        if (ohi) {
            __nv_bfloat16 hi, lo;
            split32(o, hi, lo);
            ohi[rb + c] = hi; olo[rb + c] = lo;
        }
    }
}

// ---------------------------------------------------------------------------
// Launch
// ---------------------------------------------------------------------------
extern "C" void kernel_launch(void* const* d_in, const int* in_sizes, int n_in,
                              void* d_out, int out_size) {
    const float* ff    = (const float*)d_in[0];
    const int*   fi    = (const int*)d_in[1];
    const float* w_qkv = (const float*)d_in[2];
    const float* b_qkv = (const float*)d_in[3];
    const float* w_out = (const float*)d_in[4];
    const float* b_out = (const float*)d_in[5];
    const float* w1    = (const float*)d_in[6];
    const float* b1    = (const float*)d_in[7];
    const float* w2    = (const float*)d_in[8];
    const float* b2    = (const float*)d_in[9];
    const float* g1    = (const float*)d_in[10];
    const float* bet1  = (const float*)d_in[11];
    const float* g2    = (const float*)d_in[12];
    const float* bet2  = (const float*)d_in[13];
    float* out         = (float*)d_out;

    float *px, *pqkv, *pproj, *ph, *pf2;
    __nv_bfloat16 *pxhi, *pxlo, *paohi, *paolo, *phhi, *phlo, *pf1hi, *pf1lo;
    __nv_bfloat16 *pwqkvhi, *pwqkvlo, *pwouthi, *pwoutlo, *pw1hi, *pw1lo, *pw2hi, *pw2lo;
    cudaGetSymbolAddress((void**)&px, g_x);
    cudaGetSymbolAddress((void**)&pxhi, g_xhi);
    cudaGetSymbolAddress((void**)&pxlo, g_xlo);
    cudaGetSymbolAddress((void**)&pqkv, g_qkv);
    cudaGetSymbolAddress((void**)&paohi, g_aohi);
    cudaGetSymbolAddress((void**)&paolo, g_aolo);
    cudaGetSymbolAddress((void**)&pproj, g_proj);
    cudaGetSymbolAddress((void**)&ph, g_h);
    cudaGetSymbolAddress((void**)&phhi, g_hhi);
    cudaGetSymbolAddress((void**)&phlo, g_hlo);
    cudaGetSymbolAddress((void**)&pf1hi, g_f1hi);
    cudaGetSymbolAddress((void**)&pf1lo, g_f1lo);
    cudaGetSymbolAddress((void**)&pf2, g_f2);
    cudaGetSymbolAddress((void**)&pwqkvhi, g_wqkvhi);
    cudaGetSymbolAddress((void**)&pwqkvlo, g_wqkvlo);
    cudaGetSymbolAddress((void**)&pwouthi, g_wouthi);
    cudaGetSymbolAddress((void**)&pwoutlo, g_woutlo);
    cudaGetSymbolAddress((void**)&pw1hi, g_w1hi);
    cudaGetSymbolAddress((void**)&pw1lo, g_w1lo);
    cudaGetSymbolAddress((void**)&pw2hi, g_w2hi);
    cudaGetSymbolAddress((void**)&pw2lo, g_w2lo);

    cudaFuncSetAttribute(gemm_mma, cudaFuncAttributeMaxDynamicSharedMemorySize, GSMEM_BYTES);

    // weight splits (vectorized x4)
    split_kernel<<<(D3 * DD / 4 + 255) / 256, 256>>>(w_qkv, pwqkvhi, pwqkvlo, D3 * DD / 4);
    split_kernel<<<(DD * DD / 4 + 255) / 256, 256>>>(w_out, pwouthi, pwoutlo, DD * DD / 4);
    split_kernel<<<(D4 * DD / 4 + 255) / 256, 256>>>(w1, pw1hi, pw1lo, D4 * DD / 4);
    split_kernel<<<(DD * D4 / 4 + 255) / 256, 256>>>(w2, pw2hi, pw2lo, DD * D4 / 4);

    // 1) PE add + split (pairwise)
    pe_add_kernel<<<(MTOK * DD / 2) / 256, 256>>>(ff, fi, px, pxhi, pxlo);

    // 2) QKV projection (fp32 out for attention)
    gemm_mma<<<dim3(D3 / BN, MTOK / BM), 256, GSMEM_BYTES>>>(
        pxhi, pxlo, pwqkvhi, pwqkvlo, b_qkv, pqkv, nullptr, nullptr, D3, DD, 0);

    // 3) windowed attention -> ao hi/lo
    attn_win_kernel<<<dim3(HH, NWIN, BB), 256>>>(pqkv, paohi, paolo);

    // 4) out projection (fp32 out for residual)
    gemm_mma<<<dim3(DD / BN, MTOK / BM), 256, GSMEM_BYTES>>>(
        paohi, paolo, pwouthi, pwoutlo, b_out, pproj, nullptr, nullptr, DD, DD, 0);

    // 5) LN1(x + proj) -> h fp32 + hi/lo
    ln_add_kernel<<<MTOK, 256>>>(px, pproj, g1, bet1, ph, phhi, phlo);

    // 6) FFN1 + GELU -> f1 hi/lo (bf16 only)
    gemm_mma<<<dim3(D4 / BN, MTOK / BM), 256, GSMEM_BYTES>>>(
        phhi, phlo, pw1hi, pw1lo, b1, nullptr, pf1hi, pf1lo, D4, DD, 1);

    // 7) FFN2 -> f2 fp32
    gemm_mma<<<dim3(DD / BN, MTOK / BM), 256, GSMEM_BYTES>>>(
        pf1hi, pf1lo, pw2hi, pw2lo, b2, pf2, nullptr, nullptr, DD, D4, 0);

    // 8) LN2(h + f2) -> out
    ln_add_kernel<<<MTOK, 256>>>(ph, pf2, g2, bet2, out, nullptr, nullptr);
}

// round 12
// speedup vs baseline: 2.9671x; 1.1619x over previous
#include <cuda_runtime.h>
#include <cuda_bf16.h>
#include <stdint.h>
#include <math.h>

// Problem constants
#define BB 8
#define TT 2048
#define DD 1024
#define WW 16
#define HH 8
#define HDIM 128
#define NWIN (TT / WW)
#define MTOK (BB * TT)          // 16384
#define D4 (4 * DD)             // 4096
#define D3 (3 * DD)             // 3072

// bf16 GEMM tiling
#define BM 128
#define BN 128
#define BK 32
#define RSB 80                  // smem row stride bytes (32 bf16 -> 64B, padded)
#define REG_A 0
#define REG_AL 10240
#define REG_B 20480
#define REG_BL 30720
#define SBUF 40960
#define GSMEM_BYTES (2 * SBUF)  // 81920

// tf32 GEMM tiling
#define TRS 36                  // row stride in floats (32 + 4 pad)
#define TSA (128 * TRS * 4)     // 18432 bytes per tile
#define TSBUF (2 * TSA)         // 36864
#define TGSMEM (2 * TSBUF)      // 73728

// ---------------------------------------------------------------------------
// Scratch (__device__ globals; allocation-free)
// ---------------------------------------------------------------------------
__device__ float g_x[MTOK * DD];
__device__ __nv_bfloat16 g_xhi[MTOK * DD], g_xlo[MTOK * DD];
__device__ float g_qkv[MTOK * D3];
__device__ __nv_bfloat16 g_aohi[MTOK * DD], g_aolo[MTOK * DD];
__device__ float g_proj[MTOK * DD];
__device__ float g_h[MTOK * DD];
__device__ float g_ht[MTOK * DD];       // tf32-rounded copy of h
__device__ float g_f1t[MTOK * D4];      // tf32-rounded gelu(FFN1)
__device__ float g_f2[MTOK * DD];
__device__ __nv_bfloat16 g_wqkvhi[D3 * DD], g_wqkvlo[D3 * DD];
__device__ __nv_bfloat16 g_wouthi[DD * DD], g_woutlo[DD * DD];
__device__ float g_w1t[D4 * DD];        // tf32-rounded w1
__device__ float g_w2t[DD * D4];        // tf32-rounded w2

// ---------------------------------------------------------------------------
// Helpers
// ---------------------------------------------------------------------------
__device__ __forceinline__ uint32_t smem_u32(const void* p) {
    uint32_t a;
    asm("{ .reg .u64 t; cvta.to.shared.u64 t, %1; cvt.u32.u64 %0, t; }"
        : "=r"(a) : "l"(p));
    return a;
}
#define CP_ASYNC16(dst, src) \
    asm volatile("cp.async.cg.shared.global [%0], [%1], 16;" :: "r"(dst), "l"(src))
#define CP_COMMIT() asm volatile("cp.async.commit_group;" ::: "memory")
#define CP_WAIT0() asm volatile("cp.async.wait_group 0;" ::: "memory")
#define LDSM4(r0, r1, r2, r3, addr) \
    asm volatile("ldmatrix.sync.aligned.m8n8.x4.shared.b16 {%0,%1,%2,%3}, [%4];" \
                 : "=r"(r0), "=r"(r1), "=r"(r2), "=r"(r3) : "r"(addr))
#define MMA16816(d, a, b0, b1) \
    asm volatile("mma.sync.aligned.m16n8k16.row.col.f32.bf16.bf16.f32 " \
                 "{%0,%1,%2,%3},{%4,%5,%6,%7},{%8,%9},{%0,%1,%2,%3};" \
                 : "+f"((d)[0]), "+f"((d)[1]), "+f"((d)[2]), "+f"((d)[3]) \
                 : "r"((a)[0]), "r"((a)[1]), "r"((a)[2]), "r"((a)[3]), \
                   "r"(b0), "r"(b1))
#define MMATF32(d, a, b0, b1) \
    asm volatile("mma.sync.aligned.m16n8k8.row.col.f32.tf32.tf32.f32 " \
                 "{%0,%1,%2,%3},{%4,%5,%6,%7},{%8,%9},{%0,%1,%2,%3};" \
                 : "+f"((d)[0]), "+f"((d)[1]), "+f"((d)[2]), "+f"((d)[3]) \
                 : "r"((a)[0]), "r"((a)[1]), "r"((a)[2]), "r"((a)[3]), \
                   "r"(b0), "r"(b1))

__device__ __forceinline__ void split32(float v, __nv_bfloat16& hi, __nv_bfloat16& lo) {
    hi = __float2bfloat16(v);
    lo = __float2bfloat16(v - __bfloat162float(hi));
}
__device__ __forceinline__ float tf32r(float v) {
    float o;
    asm("cvt.rna.tf32.f32 %0, %1;" : "=f"(o) : "f"(v));
    return o;
}
__device__ __forceinline__ float gelu_exact(float v) {
    return v * 0.5f * (1.0f + erff(v * 0.7071067811865476f));
}

// ---------------------------------------------------------------------------
// bf16x3 GEMM (QKV / out-proj): C = A*B^T + bias, fp32 out.
// Single __syncthreads per chunk.
// ---------------------------------------------------------------------------
__global__ __launch_bounds__(256, 2)
void gemm_mma(const __nv_bfloat16* __restrict__ Ahi, const __nv_bfloat16* __restrict__ Alo,
              const __nv_bfloat16* __restrict__ Bhi, const __nv_bfloat16* __restrict__ Blo,
              const float* __restrict__ bias, float* __restrict__ Cf,
              int N, int K) {
    extern __shared__ char smem[];
    const uint32_t sbase = smem_u32(smem);
    const int tid = threadIdx.x;
    const int w = tid >> 5;
    const int lane = tid & 31;
    const int warp_m = (w >> 2) * 64;
    const int warp_n = (w & 3) * 32;
    const int bm = blockIdx.y * BM;
    const int bn = blockIdx.x * BN;

    float acc[4][4][4];
#pragma unroll
    for (int i = 0; i < 4; i++)
#pragma unroll
        for (int j = 0; j < 4; j++)
#pragma unroll
            for (int q = 0; q < 4; q++) acc[i][j][q] = 0.0f;

    const int nc = K / BK;
    const int lr = tid >> 2;
    const int lc16 = tid & 3;
    const __nv_bfloat16* pAh = Ahi + (size_t)(bm + lr) * K + lc16 * 8;
    const __nv_bfloat16* pAl = Alo + (size_t)(bm + lr) * K + lc16 * 8;
    const __nv_bfloat16* pBh = Bhi + (size_t)(bn + lr) * K + lc16 * 8;
    const __nv_bfloat16* pBl = Blo + (size_t)(bn + lr) * K + lc16 * 8;
    const size_t rsk = (size_t)64 * K;
    const uint32_t dsto = lr * RSB + lc16 * 16;

    auto load_chunk = [&](int c, int buf) {
        const uint32_t db = sbase + buf * SBUF + dsto;
        const size_t ko = (size_t)c * BK;
        CP_ASYNC16(db + REG_A, pAh + ko);
        CP_ASYNC16(db + REG_A + 64 * RSB, pAh + rsk + ko);
        CP_ASYNC16(db + REG_AL, pAl + ko);
        CP_ASYNC16(db + REG_AL + 64 * RSB, pAl + rsk + ko);
        CP_ASYNC16(db + REG_B, pBh + ko);
        CP_ASYNC16(db + REG_B + 64 * RSB, pBh + rsk + ko);
        CP_ASYNC16(db + REG_BL, pBl + ko);
        CP_ASYNC16(db + REG_BL + 64 * RSB, pBl + rsk + ko);
    };

    load_chunk(0, 0);
    CP_COMMIT();

    const int j8 = lane >> 3;
    const int l7 = lane & 7;

    for (int c = 0; c < nc; c++) {
        const int buf = c & 1;
        CP_WAIT0();
        __syncthreads();            // publishes chunk c; frees buf^1
        if (c + 1 < nc) {
            load_chunk(c + 1, buf ^ 1);
            CP_COMMIT();
        }

        const uint32_t db = sbase + buf * SBUF;
#pragma unroll
        for (int ks = 0; ks < 2; ks++) {
            uint32_t bh[4][2];
#pragma unroll
            for (int p = 0; p < 2; p++) {
                int brow = warp_n + p * 16 + ((j8 >> 1) << 3) + l7;
                int bc16 = ks * 2 + (j8 & 1);
                uint32_t ab = db + REG_B + brow * RSB + bc16 * 16;
                LDSM4(bh[p * 2][0], bh[p * 2][1], bh[p * 2 + 1][0], bh[p * 2 + 1][1], ab);
            }
            uint32_t af[4][4];
#pragma unroll
            for (int mt = 0; mt < 4; mt++) {
                int arow = warp_m + mt * 16 + ((j8 & 1) << 3) + l7;
                int ac16 = ks * 2 + (j8 >> 1);
                uint32_t aa = db + REG_A + arow * RSB + ac16 * 16;
                LDSM4(af[mt][0], af[mt][1], af[mt][2], af[mt][3], aa);
            }
#pragma unroll
            for (int mt = 0; mt < 4; mt++)
#pragma unroll
                for (int nt = 0; nt < 4; nt++)
                    MMA16816(acc[mt][nt], af[mt], bh[nt][0], bh[nt][1]);
            uint32_t bl[4][2];
#pragma unroll
            for (int p = 0; p < 2; p++) {
                int brow = warp_n + p * 16 + ((j8 >> 1) << 3) + l7;
                int bc16 = ks * 2 + (j8 & 1);
                uint32_t abl = db + REG_BL + brow * RSB + bc16 * 16;
                LDSM4(bl[p * 2][0], bl[p * 2][1], bl[p * 2 + 1][0], bl[p * 2 + 1][1], abl);
            }
#pragma unroll
            for (int mt = 0; mt < 4; mt++)
#pragma unroll
                for (int nt = 0; nt < 4; nt++)
                    MMA16816(acc[mt][nt], af[mt], bl[nt][0], bl[nt][1]);
#pragma unroll
            for (int mt = 0; mt < 4; mt++) {
                int arow = warp_m + mt * 16 + ((j8 & 1) << 3) + l7;
                int ac16 = ks * 2 + (j8 >> 1);
                uint32_t aa = db + REG_AL + arow * RSB + ac16 * 16;
                LDSM4(af[mt][0], af[mt][1], af[mt][2], af[mt][3], aa);
            }
#pragma unroll
            for (int mt = 0; mt < 4; mt++)
#pragma unroll
                for (int nt = 0; nt < 4; nt++)
                    MMA16816(acc[mt][nt], af[mt], bh[nt][0], bh[nt][1]);
        }
    }

    // epilogue: fp32 out
    const int g4 = lane >> 2;
    const int q2 = (lane & 3) * 2;
#pragma unroll
    for (int mt = 0; mt < 4; mt++) {
#pragma unroll
        for (int half = 0; half < 2; half++) {
            int row = bm + warp_m + mt * 16 + g4 + half * 8;
#pragma unroll
            for (int nt = 0; nt < 4; nt++) {
                int col = bn + warp_n + nt * 8 + q2;
                float2 o;
                o.x = acc[mt][nt][half * 2 + 0] + __ldg(&bias[col + 0]);
                o.y = acc[mt][nt][half * 2 + 1] + __ldg(&bias[col + 1]);
                *(float2*)&Cf[(size_t)row * N + col] = o;
            }
        }
    }
}

// ---------------------------------------------------------------------------
// tf32 single-pass GEMM (FFN): C = A*B^T + bias. Operands pre-rounded tf32.
// mode 0: fp32 out. mode 1: gelu -> tf32-rounded fp32 out.
// ---------------------------------------------------------------------------
__global__ __launch_bounds__(256, 2)
void gemm_tf32(const float* __restrict__ A, const float* __restrict__ Bm,
               const float* __restrict__ bias, float* __restrict__ Cf,
               int N, int K, int mode) {
    extern __shared__ char smem[];
    const uint32_t sbase = smem_u32(smem);
    const int tid = threadIdx.x;
    const int w = tid >> 5;
    const int lane = tid & 31;
    const int warp_m = (w >> 2) * 64;
    const int warp_n = (w & 3) * 32;
    const int bm = blockIdx.y * BM;
    const int bn = blockIdx.x * BN;

    float acc[4][4][4];
#pragma unroll
    for (int i = 0; i < 4; i++)
#pragma unroll
        for (int j = 0; j < 4; j++)
#pragma unroll
            for (int q = 0; q < 4; q++) acc[i][j][q] = 0.0f;

    const int nc = K / BK;
    const int lr = tid >> 3;        // 0..31
    const int lc = tid & 7;         // 16B col 0..7
    const float* pA = A + (size_t)(bm + lr) * K + lc * 4;
    const float* pB = Bm + (size_t)(bn + lr) * K + lc * 4;
    const uint32_t dsto = lr * (TRS * 4) + lc * 16;

    auto load_chunk = [&](int c, int buf) {
        const uint32_t db = sbase + buf * TSBUF;
        const size_t ko = (size_t)c * BK;
#pragma unroll
        for (int wv = 0; wv < 4; wv++) {
            CP_ASYNC16(db + dsto + wv * (32 * TRS * 4), pA + (size_t)wv * 32 * K + ko);
            CP_ASYNC16(db + TSA + dsto + wv * (32 * TRS * 4), pB + (size_t)wv * 32 * K + ko);
        }
    };

    load_chunk(0, 0);
    CP_COMMIT();

    const int g = lane >> 2;
    const int l4 = lane & 3;

    for (int c = 0; c < nc; c++) {
        const int buf = c & 1;
        CP_WAIT0();
        __syncthreads();
        if (c + 1 < nc) {
            load_chunk(c + 1, buf ^ 1);
            CP_COMMIT();
        }
        const float* sA = (const float*)(smem + buf * TSBUF);
        const float* sB = (const float*)(smem + buf * TSBUF + TSA);
#pragma unroll
        for (int kk = 0; kk < 4; kk++) {
            const int k0 = kk * 8;
            uint32_t bf[4][2];
#pragma unroll
            for (int nt = 0; nt < 4; nt++) {
                int n = warp_n + nt * 8 + g;
                bf[nt][0] = __float_as_uint(sB[n * TRS + k0 + l4]);
                bf[nt][1] = __float_as_uint(sB[n * TRS + k0 + l4 + 4]);
            }
#pragma unroll
            for (int mt = 0; mt < 4; mt++) {
                int m = warp_m + mt * 16 + g;
                uint32_t af[4];
                af[0] = __float_as_uint(sA[m * TRS + k0 + l4]);
                af[1] = __float_as_uint(sA[(m + 8) * TRS + k0 + l4]);
                af[2] = __float_as_uint(sA[m * TRS + k0 + l4 + 4]);
                af[3] = __float_as_uint(sA[(m + 8) * TRS + k0 + l4 + 4]);
#pragma unroll
                for (int nt = 0; nt < 4; nt++)
                    MMATF32(acc[mt][nt], af, bf[nt][0], bf[nt][1]);
            }
        }
    }

    // epilogue
    const int q2 = l4 * 2;
#pragma unroll
    for (int mt = 0; mt < 4; mt++) {
#pragma unroll
        for (int half = 0; half < 2; half++) {
            int row = bm + warp_m + mt * 16 + g + half * 8;
#pragma unroll
            for (int nt = 0; nt < 4; nt++) {
                int col = bn + warp_n + nt * 8 + q2;
                float v0 = acc[mt][nt][half * 2 + 0] + __ldg(&bias[col + 0]);
                float v1 = acc[mt][nt][half * 2 + 1] + __ldg(&bias[col + 1]);
                float2 o;
                if (mode == 0) {
                    o.x = v0; o.y = v1;
                } else {
                    o.x = tf32r(gelu_exact(v0));
                    o.y = tf32r(gelu_exact(v1));
                }
                *(float2*)&Cf[(size_t)row * N + col] = o;
            }
        }
    }
}

// ---------------------------------------------------------------------------
// PE add: one thread per (even,odd) pair
// ---------------------------------------------------------------------------
__global__ void pe_add_kernel(const float* __restrict__ ff,
                              const int* __restrict__ idx32,
                              float* __restrict__ x,
                              __nv_bfloat16* __restrict__ xhi,
                              __nv_bfloat16* __restrict__ xlo) {
    int p = blockIdx.x * blockDim.x + threadIdx.x;
    int tok = p >> 9;
    int d = (p & 511) << 1;
    bool is64 = (idx32[1] == 0);
    float pos = (float)(is64 ? idx32[2 * tok] : idx32[tok]);
    float ang = pos * expf(-9.210340371976184f * (float)d / (float)DD);
    float s, c;
    sincosf(ang, &s, &c);
    size_t i = (size_t)p * 2;
    float2 f = *(const float2*)&ff[i];
    float v0 = f.x + s;
    float v1 = f.y + c;
    *(float2*)&x[i] = make_float2(v0, v1);
    __nv_bfloat16 h0, l0, h1, l1;
    split32(v0, h0, l0);
    split32(v1, h1, l1);
    __nv_bfloat162 ph; ph.x = h0; ph.y = h1;
    __nv_bfloat162 pl; pl.x = l0; pl.y = l1;
    *(__nv_bfloat162*)&xhi[i] = ph;
    *(__nv_bfloat162*)&xlo[i] = pl;
}

// ---------------------------------------------------------------------------
// Weight split (bf16 hi/lo) and tf32 rounding kernels
// ---------------------------------------------------------------------------
__global__ void split_kernel(const float* __restrict__ in,
                             __nv_bfloat16* __restrict__ hi,
                             __nv_bfloat16* __restrict__ lo, int n4) {
    int i = blockIdx.x * blockDim.x + threadIdx.x;
    if (i < n4) {
        size_t b = (size_t)i * 4;
        float4 v = *(const float4*)&in[b];
        __nv_bfloat16 h[4], l[4];
        split32(v.x, h[0], l[0]);
        split32(v.y, h[1], l[1]);
        split32(v.z, h[2], l[2]);
        split32(v.w, h[3], l[3]);
        __nv_bfloat162 p0, p1;
        p0.x = h[0]; p0.y = h[1]; p1.x = h[2]; p1.y = h[3];
        *(__nv_bfloat162*)&hi[b] = p0;
        *(__nv_bfloat162*)&hi[b + 2] = p1;
        p0.x = l[0]; p0.y = l[1]; p1.x = l[2]; p1.y = l[3];
        *(__nv_bfloat162*)&lo[b] = p0;
        *(__nv_bfloat162*)&lo[b + 2] = p1;
    }
}

__global__ void tf32_round_kernel(const float* __restrict__ in,
                                  float* __restrict__ out, int n4) {
    int i = blockIdx.x * blockDim.x + threadIdx.x;
    if (i < n4) {
        size_t b = (size_t)i * 4;
        float4 v = *(const float4*)&in[b];
        v.x = tf32r(v.x); v.y = tf32r(v.y);
        v.z = tf32r(v.z); v.w = tf32r(v.w);
        *(float4*)&out[b] = v;
    }
}

// ---------------------------------------------------------------------------
// Per-window attention (fp32), emits bf16 hi/lo of attention output
// ---------------------------------------------------------------------------
__global__ __launch_bounds__(256)
void attn_win_kernel(const float* __restrict__ qkv,
                     __nv_bfloat16* __restrict__ ohi,
                     __nv_bfloat16* __restrict__ olo) {
    __shared__ float q[16][132];
    __shared__ float k[16][132];
    __shared__ float v[16][132];
    __shared__ float s[16][16];

    const int h = blockIdx.x;
    const int n = blockIdx.y;
    const int b = blockIdx.z;
    const int tid = threadIdx.x;

    const long base = ((long)b * TT + (long)n * WW) * D3;
    const int qo = h * HDIM;
    const int ko = DD + h * HDIM;
    const int vo = 2 * DD + h * HDIM;

#pragma unroll
    for (int i = 0; i < 8; i++) {
        int e = tid + i * 256;
        int r = e >> 7;
        int d = e & 127;
        long rb = base + (long)r * D3;
        q[r][d] = qkv[rb + qo + d];
        k[r][d] = qkv[rb + ko + d];
        v[r][d] = qkv[rb + vo + d];
    }
    __syncthreads();

    {
        int qi = tid >> 4, ki = tid & 15;
        float acc = 0.0f;
#pragma unroll
        for (int d4 = 0; d4 < 32; d4++) {
            float4 qq = *(const float4*)&q[qi][d4 * 4];
            float4 kk = *(const float4*)&k[ki][d4 * 4];
            acc += qq.x * kk.x + qq.y * kk.y + qq.z * kk.z + qq.w * kk.w;
        }
        s[qi][ki] = acc * 0.08838834764831845f;
    }
    __syncthreads();

    if (tid < 16) {
        float mx = -1e30f;
#pragma unroll
        for (int j = 0; j < 16; j++) mx = fmaxf(mx, s[tid][j]);
        float p[16];
        float sum = 0.0f;
#pragma unroll
        for (int j = 0; j < 16; j++) { p[j] = expf(s[tid][j] - mx); sum += p[j]; }
        float inv = 1.0f / sum;
#pragma unroll
        for (int j = 0; j < 16; j++) s[tid][j] = p[j] * inv;
    }
    __syncthreads();

    const long obase = ((long)b * TT + (long)n * WW) * DD + h * HDIM;
#pragma unroll
    for (int i = 0; i < 8; i++) {
        int e = tid + i * 256;
        int r = e >> 7;
        int d = e & 127;
        float acc = 0.0f;
#pragma unroll
        for (int j = 0; j < 16; j++) acc += s[r][j] * v[j][d];
        __nv_bfloat16 hi, lo;
        split32(acc, hi, lo);
        long oi = obase + (long)r * DD + d;
        ohi[oi] = hi; olo[oi] = lo;
    }
}

// ---------------------------------------------------------------------------
// LayerNorm(a + b); optionally emits tf32-rounded copy of the result
// ---------------------------------------------------------------------------
__device__ __forceinline__ float warp_sum(float x) {
#pragma unroll
    for (int off = 16; off > 0; off >>= 1) x += __shfl_xor_sync(0xffffffffu, x, off);
    return x;
}

__global__ __launch_bounds__(256)
void ln_add_kernel(const float* __restrict__ a, const float* __restrict__ bres,
                   const float* __restrict__ g, const float* __restrict__ beta,
                   float* __restrict__ out, float* __restrict__ ot) {
    __shared__ float rs[8], rq[8], tot[2];
    const int row = blockIdx.x;
    const int tid = threadIdx.x;
    const long rb = (long)row * DD;

    float vals[4];
    float s = 0.0f, sq = 0.0f;
#pragma unroll
    for (int i = 0; i < 4; i++) {
        int c = tid + i * 256;
        float x = a[rb + c] + bres[rb + c];
        vals[i] = x;
        s += x;
        sq += x * x;
    }
    float ws = warp_sum(s), wq = warp_sum(sq);
    int wid = tid >> 5, lane = tid & 31;
    if (lane == 0) { rs[wid] = ws; rq[wid] = wq; }
    __syncthreads();
    if (tid == 0) {
        float ta = 0.0f, tb = 0.0f;
#pragma unroll
        for (int i = 0; i < 8; i++) { ta += rs[i]; tb += rq[i]; }
        tot[0] = ta; tot[1] = tb;
    }
    __syncthreads();
    float mean = tot[0] * (1.0f / DD);
    float var = tot[1] * (1.0f / DD) - mean * mean;
    float inv = rsqrtf(var + 1e-5f);
#pragma unroll
    for (int i = 0; i < 4; i++) {
        int c = tid + i * 256;
        float o = (vals[i] - mean) * inv * g[c] + beta[c];
        out[rb + c] = o;
        if (ot) ot[rb + c] = tf32r(o);
    }
}

// ---------------------------------------------------------------------------
// Launch
// ---------------------------------------------------------------------------
extern "C" void kernel_launch(void* const* d_in, const int* in_sizes, int n_in,
                              void* d_out, int out_size) {
    const float* ff    = (const float*)d_in[0];
    const int*   fi    = (const int*)d_in[1];
    const float* w_qkv = (const float*)d_in[2];
    const float* b_qkv = (const float*)d_in[3];
    const float* w_out = (const float*)d_in[4];
    const float* b_out = (const float*)d_in[5];
    const float* w1    = (const float*)d_in[6];
    const float* b1    = (const float*)d_in[7];
    const float* w2    = (const float*)d_in[8];
    const float* b2    = (const float*)d_in[9];
    const float* g1    = (const float*)d_in[10];
    const float* bet1  = (const float*)d_in[11];
    const float* g2    = (const float*)d_in[12];
    const float* bet2  = (const float*)d_in[13];
    float* out         = (float*)d_out;

    float *px, *pqkv, *pproj, *ph, *pht, *pf1t, *pf2, *pw1t, *pw2t;
    __nv_bfloat16 *pxhi, *pxlo, *paohi, *paolo;
    __nv_bfloat16 *pwqkvhi, *pwqkvlo, *pwouthi, *pwoutlo;
    cudaGetSymbolAddress((void**)&px, g_x);
    cudaGetSymbolAddress((void**)&pxhi, g_xhi);
    cudaGetSymbolAddress((void**)&pxlo, g_xlo);
    cudaGetSymbolAddress((void**)&pqkv, g_qkv);
    cudaGetSymbolAddress((void**)&paohi, g_aohi);
    cudaGetSymbolAddress((void**)&paolo, g_aolo);
    cudaGetSymbolAddress((void**)&pproj, g_proj);
    cudaGetSymbolAddress((void**)&ph, g_h);
    cudaGetSymbolAddress((void**)&pht, g_ht);
    cudaGetSymbolAddress((void**)&pf1t, g_f1t);
    cudaGetSymbolAddress((void**)&pf2, g_f2);
    cudaGetSymbolAddress((void**)&pwqkvhi, g_wqkvhi);
    cudaGetSymbolAddress((void**)&pwqkvlo, g_wqkvlo);
    cudaGetSymbolAddress((void**)&pwouthi, g_wouthi);
    cudaGetSymbolAddress((void**)&pwoutlo, g_woutlo);
    cudaGetSymbolAddress((void**)&pw1t, g_w1t);
    cudaGetSymbolAddress((void**)&pw2t, g_w2t);

    cudaFuncSetAttribute(gemm_mma, cudaFuncAttributeMaxDynamicSharedMemorySize, GSMEM_BYTES);
    cudaFuncSetAttribute(gemm_tf32, cudaFuncAttributeMaxDynamicSharedMemorySize, TGSMEM);

    // weight prep
    split_kernel<<<(D3 * DD / 4 + 255) / 256, 256>>>(w_qkv, pwqkvhi, pwqkvlo, D3 * DD / 4);
    split_kernel<<<(DD * DD / 4 + 255) / 256, 256>>>(w_out, pwouthi, pwoutlo, DD * DD / 4);
    tf32_round_kernel<<<(D4 * DD / 4 + 255) / 256, 256>>>(w1, pw1t, D4 * DD / 4);
    tf32_round_kernel<<<(DD * D4 / 4 + 255) / 256, 256>>>(w2, pw2t, DD * D4 / 4);

    // 1) PE add + bf16 split
    pe_add_kernel<<<(MTOK * DD / 2) / 256, 256>>>(ff, fi, px, pxhi, pxlo);

    // 2) QKV projection (bf16x3)
    gemm_mma<<<dim3(D3 / BN, MTOK / BM), 256, GSMEM_BYTES>>>(
        pxhi, pxlo, pwqkvhi, pwqkvlo, b_qkv, pqkv, D3, DD);

    // 3) windowed attention -> ao hi/lo
    attn_win_kernel<<<dim3(HH, NWIN, BB), 256>>>(pqkv, paohi, paolo);

    // 4) out projection (bf16x3)
    gemm_mma<<<dim3(DD / BN, MTOK / BM), 256, GSMEM_BYTES>>>(
        paohi, paolo, pwouthi, pwoutlo, b_out, pproj, DD, DD);

    // 5) LN1(x + proj) -> h fp32 + tf32 copy
    ln_add_kernel<<<MTOK, 256>>>(px, pproj, g1, bet1, ph, pht);

    // 6) FFN1 + GELU (tf32 single pass) -> f1 tf32-rounded fp32
    gemm_tf32<<<dim3(D4 / BN, MTOK / BM), 256, TGSMEM>>>(
        pht, pw1t, b1, pf1t, D4, DD, 1);

    // 7) FFN2 (tf32 single pass) -> f2 fp32
    gemm_tf32<<<dim3(DD / BN, MTOK / BM), 256, TGSMEM>>>(
        pf1t, pw2t, b2, pf2, DD, D4, 0);

    // 8) LN2(h + f2) -> out
    ln_add_kernel<<<MTOK, 256>>>(ph, pf2, g2, bet2, out, nullptr);
}

// round 13
// speedup vs baseline: 3.6978x; 1.2463x over previous
#include <cuda_runtime.h>
#include <cuda_bf16.h>
#include <stdint.h>
#include <math.h>

// Problem constants
#define BB 8
#define TT 2048
#define DD 1024
#define WW 16
#define HH 8
#define HDIM 128
#define NWIN (TT / WW)
#define MTOK (BB * TT)          // 16384
#define D4 (4 * DD)             // 4096
#define D3 (3 * DD)             // 3072

// tf32 GEMM tiling
#define BM 128
#define BN 128
#define BK 32
#define TRS 40                  // smem row stride in floats (32 + 8 pad)
#define TSA (128 * TRS * 4)     // 20480 bytes per tile
#define TSBUF (2 * TSA)         // 40960 (A + B)
#define TGSMEM (2 * TSBUF)      // 81920 ; x2 CTAs/SM = 163840 <= 227KB

// ---------------------------------------------------------------------------
// Scratch (__device__ globals; allocation-free)
// All "t" buffers are tf32-rounded AND K-permuted (slot layout per 8-group:
// [k0,k4,k1,k5,k2,k6,k3,k7]) for paired ld.shared.v2 fragment loads.
// ---------------------------------------------------------------------------
__device__ float g_x[MTOK * DD];        // exact x (residual)
__device__ float g_xt[MTOK * DD];       // tf32+perm x (QKV A)
__device__ float g_qkv[MTOK * D3];      // fp32 QKV (attention input)
__device__ float g_aot[MTOK * DD];      // tf32+perm attention out (out-proj A)
__device__ float g_proj[MTOK * DD];     // fp32 out-proj (residual)
__device__ float g_h[MTOK * DD];        // exact h (residual)
__device__ float g_ht[MTOK * DD];       // tf32+perm h (FFN1 A)
__device__ float g_f1t[MTOK * D4];      // tf32+perm gelu(FFN1) (FFN2 A)
__device__ float g_f2[MTOK * DD];       // fp32 FFN2 out
__device__ float g_wqkvt[D3 * DD];      // tf32+perm weights
__device__ float g_woutt[DD * DD];
__device__ float g_w1t[D4 * DD];
__device__ float g_w2t[DD * D4];

// ---------------------------------------------------------------------------
// Helpers
// ---------------------------------------------------------------------------
__device__ __forceinline__ uint32_t smem_u32(const void* p) {
    uint32_t a;
    asm("{ .reg .u64 t; cvta.to.shared.u64 t, %1; cvt.u32.u64 %0, t; }"
        : "=r"(a) : "l"(p));
    return a;
}
#define CP_ASYNC16(dst, src) \
    asm volatile("cp.async.cg.shared.global [%0], [%1], 16;" :: "r"(dst), "l"(src))
#define CP_COMMIT() asm volatile("cp.async.commit_group;" ::: "memory")
#define CP_WAIT0() asm volatile("cp.async.wait_group 0;" ::: "memory")
#define LDS64(r0, r1, addr) \
    asm volatile("ld.shared.v2.b32 {%0,%1}, [%2];" : "=r"(r0), "=r"(r1) : "r"(addr))
#define MMATF32(d, a0, a1, a2, a3, b0, b1) \
    asm volatile("mma.sync.aligned.m16n8k8.row.col.f32.tf32.tf32.f32 " \
                 "{%0,%1,%2,%3},{%4,%5,%6,%7},{%8,%9},{%0,%1,%2,%3};" \
                 : "+f"((d)[0]), "+f"((d)[1]), "+f"((d)[2]), "+f"((d)[3]) \
                 : "r"(a0), "r"(a1), "r"(a2), "r"(a3), "r"(b0), "r"(b1))

__device__ __forceinline__ float tf32r(float v) {
    float o;
    asm("cvt.rna.tf32.f32 %0, %1;" : "=f"(o) : "f"(v));
    return o;
}
__device__ __forceinline__ float gelu_exact(float v) {
    return v * 0.5f * (1.0f + erff(v * 0.7071067811865476f));
}
// K permutation within 8-groups: slot of original column c
__device__ __forceinline__ int kperm(int c) {
    return (c & ~7) | (((c & 3) << 1) | ((c & 7) >> 2));
}

// ---------------------------------------------------------------------------
// tf32 single-pass GEMM: C[m][n] = sum_k A[m][k]*B[n][k] + bias[n]
// A,B tf32-rounded + K-permuted. 128x128 CTA tile, 8 warps (64x32 warp tile),
// BK=32, cp.async double buffer, one __syncthreads per chunk.
// mode 0: fp32 out. mode 1: gelu -> tf32-rounded, K-permuted fp32 out.
// ---------------------------------------------------------------------------
__global__ __launch_bounds__(256, 2)
void gemm_tf32(const float* __restrict__ A, const float* __restrict__ Bm,
               const float* __restrict__ bias, float* __restrict__ Cf,
               int N, int K, int mode) {
    extern __shared__ char smem[];
    const uint32_t sbase = smem_u32(smem);
    const int tid = threadIdx.x;
    const int w = tid >> 5;
    const int lane = tid & 31;
    const int warp_m = (w >> 2) * 64;
    const int warp_n = (w & 3) * 32;
    const int bm = blockIdx.y * BM;
    const int bn = blockIdx.x * BN;

    float acc[4][4][4];
#pragma unroll
    for (int i = 0; i < 4; i++)
#pragma unroll
        for (int j = 0; j < 4; j++)
#pragma unroll
            for (int q = 0; q < 4; q++) acc[i][j][q] = 0.0f;

    const int nc = K / BK;
    const int lr = tid >> 3;        // 0..31
    const int lc = tid & 7;         // 16B col 0..7
    const float* pA = A + (size_t)(bm + lr) * K + lc * 4;
    const float* pB = Bm + (size_t)(bn + lr) * K + lc * 4;
    const uint32_t dsto = lr * (TRS * 4) + lc * 16;

    auto load_chunk = [&](int c, int buf) {
        const uint32_t db = sbase + buf * TSBUF;
        const size_t ko = (size_t)c * BK;
#pragma unroll
        for (int wv = 0; wv < 4; wv++) {
            CP_ASYNC16(db + dsto + wv * (32 * TRS * 4), pA + (size_t)wv * 32 * K + ko);
            CP_ASYNC16(db + TSA + dsto + wv * (32 * TRS * 4), pB + (size_t)wv * 32 * K + ko);
        }
    };

    load_chunk(0, 0);
    CP_COMMIT();

    const int g = lane >> 2;        // 0..7
    const int l4 = lane & 3;        // 0..3

    for (int c = 0; c < nc; c++) {
        const int buf = c & 1;
        CP_WAIT0();
        __syncthreads();            // publishes chunk c; frees buf^1
        if (c + 1 < nc) {
            load_chunk(c + 1, buf ^ 1);
            CP_COMMIT();
        }
        const uint32_t sA = sbase + buf * TSBUF;
        const uint32_t sB = sA + TSA;
#pragma unroll
        for (int kk = 0; kk < 4; kk++) {
            const int k0 = kk * 8;
            const uint32_t kof = (k0 + 2 * l4) * 4;
            // B fragments: slot pair (2*l4, 2*l4+1) = (k0+l4, k0+l4+4)
            uint32_t bf[4][2];
#pragma unroll
            for (int nt = 0; nt < 4; nt++) {
                int n = warp_n + nt * 8 + g;
                LDS64(bf[nt][0], bf[nt][1], sB + n * (TRS * 4) + kof);
            }
#pragma unroll
            for (int mt = 0; mt < 4; mt++) {
                int m = warp_m + mt * 16 + g;
                uint32_t a0, a2, a1, a3;
                LDS64(a0, a2, sA + m * (TRS * 4) + kof);
                LDS64(a1, a3, sA + (m + 8) * (TRS * 4) + kof);
#pragma unroll
                for (int nt = 0; nt < 4; nt++)
                    MMATF32(acc[mt][nt], a0, a1, a2, a3, bf[nt][0], bf[nt][1]);
            }
        }
    }

    // epilogue
    const int q2 = l4 * 2;
#pragma unroll
    for (int mt = 0; mt < 4; mt++) {
#pragma unroll
        for (int half = 0; half < 2; half++) {
            int row = bm + warp_m + mt * 16 + g + half * 8;
#pragma unroll
            for (int nt = 0; nt < 4; nt++) {
                int col = bn + warp_n + nt * 8 + q2;
                float v0 = acc[mt][nt][half * 2 + 0] + __ldg(&bias[col + 0]);
                float v1 = acc[mt][nt][half * 2 + 1] + __ldg(&bias[col + 1]);
                if (mode == 0) {
                    float2 o; o.x = v0; o.y = v1;
                    *(float2*)&Cf[(size_t)row * N + col] = o;
                } else {
                    // gelu + tf32 round + K-permuted scatter (feeds next GEMM's A)
                    Cf[(size_t)row * N + kperm(col)] = tf32r(gelu_exact(v0));
                    Cf[(size_t)row * N + kperm(col + 1)] = tf32r(gelu_exact(v1));
                }
            }
        }
    }
}

// ---------------------------------------------------------------------------
// PE add: x = ff + PE (exact fp32) and xt (tf32 + K-permuted)
// ---------------------------------------------------------------------------
__global__ void pe_add_kernel(const float* __restrict__ ff,
                              const int* __restrict__ idx32,
                              float* __restrict__ x,
                              float* __restrict__ xt) {
    int p = blockIdx.x * blockDim.x + threadIdx.x;
    int tok = p >> 9;
    int d = (p & 511) << 1;         // even d 0..1022
    bool is64 = (idx32[1] == 0);
    float pos = (float)(is64 ? idx32[2 * tok] : idx32[tok]);
    float ang = pos * expf(-9.210340371976184f * (float)d / (float)DD);
    float s, c;
    sincosf(ang, &s, &c);
    size_t i = (size_t)p * 2;
    float2 f = *(const float2*)&ff[i];
    float v0 = f.x + s;
    float v1 = f.y + c;
    *(float2*)&x[i] = make_float2(v0, v1);
    size_t rb = (size_t)tok * DD;
    xt[rb + kperm(d)] = tf32r(v0);
    xt[rb + kperm(d + 1)] = tf32r(v1);
}

// ---------------------------------------------------------------------------
// Weight round + permute: tf32-round and K-permute (per 8-group)
// ---------------------------------------------------------------------------
__global__ void round_perm_kernel(const float* __restrict__ in,
                                  float* __restrict__ out, int n4) {
    int i = blockIdx.x * blockDim.x + threadIdx.x;
    if (i < n4) {
        size_t b = (size_t)i * 4;
        float4 v = *(const float4*)&in[b];
        size_t base = (b & ~(size_t)7) + ((b & 4) ? 1 : 0);
        out[base + 0] = tf32r(v.x);
        out[base + 2] = tf32r(v.y);
        out[base + 4] = tf32r(v.z);
        out[base + 6] = tf32r(v.w);
    }
}

// ---------------------------------------------------------------------------
// Per-window attention (fp32) -> aot (tf32 + K-permuted)
// ---------------------------------------------------------------------------
__global__ __launch_bounds__(256)
void attn_win_kernel(const float* __restrict__ qkv, float* __restrict__ aot) {
    __shared__ float q[16][132];
    __shared__ float k[16][132];
    __shared__ float v[16][132];
    __shared__ float s[16][16];

    const int h = blockIdx.x;
    const int n = blockIdx.y;
    const int b = blockIdx.z;
    const int tid = threadIdx.x;

    const long base = ((long)b * TT + (long)n * WW) * D3;
    const int qo = h * HDIM;
    const int ko = DD + h * HDIM;
    const int vo = 2 * DD + h * HDIM;

#pragma unroll
    for (int i = 0; i < 8; i++) {
        int e = tid + i * 256;
        int r = e >> 7;
        int d = e & 127;
        long rb = base + (long)r * D3;
        q[r][d] = qkv[rb + qo + d];
        k[r][d] = qkv[rb + ko + d];
        v[r][d] = qkv[rb + vo + d];
    }
    __syncthreads();

    {
        int qi = tid >> 4, ki = tid & 15;
        float acc = 0.0f;
#pragma unroll
        for (int d4 = 0; d4 < 32; d4++) {
            float4 qq = *(const float4*)&q[qi][d4 * 4];
            float4 kk = *(const float4*)&k[ki][d4 * 4];
            acc += qq.x * kk.x + qq.y * kk.y + qq.z * kk.z + qq.w * kk.w;
        }
        s[qi][ki] = acc * 0.08838834764831845f;
    }
    __syncthreads();

    if (tid < 16) {
        float mx = -1e30f;
#pragma unroll
        for (int j = 0; j < 16; j++) mx = fmaxf(mx, s[tid][j]);
        float p[16];
        float sum = 0.0f;
#pragma unroll
        for (int j = 0; j < 16; j++) { p[j] = expf(s[tid][j] - mx); sum += p[j]; }
        float inv = 1.0f / sum;
#pragma unroll
        for (int j = 0; j < 16; j++) s[tid][j] = p[j] * inv;
    }
    __syncthreads();

    const long obase = ((long)b * TT + (long)n * WW) * DD;
#pragma unroll
    for (int i = 0; i < 8; i++) {
        int e = tid + i * 256;
        int r = e >> 7;
        int d = e & 127;
        float acc = 0.0f;
#pragma unroll
        for (int j = 0; j < 16; j++) acc += s[r][j] * v[j][d];
        aot[obase + (long)r * DD + h * HDIM + kperm(d)] = tf32r(acc);
    }
}

// ---------------------------------------------------------------------------
// LayerNorm(a + b); optionally emits tf32+K-permuted copy
// ---------------------------------------------------------------------------
__device__ __forceinline__ float warp_sum(float x) {
#pragma unroll
    for (int off = 16; off > 0; off >>= 1) x += __shfl_xor_sync(0xffffffffu, x, off);
    return x;
}

__global__ __launch_bounds__(256)
void ln_add_kernel(const float* __restrict__ a, const float* __restrict__ bres,
                   const float* __restrict__ g, const float* __restrict__ beta,
                   float* __restrict__ out, float* __restrict__ ot) {
    __shared__ float rs[8], rq[8], tot[2];
    const int row = blockIdx.x;
    const int tid = threadIdx.x;
    const long rb = (long)row * DD;

    float vals[4];
    float s = 0.0f, sq = 0.0f;
#pragma unroll
    for (int i = 0; i < 4; i++) {
        int c = tid + i * 256;
        float x = a[rb + c] + bres[rb + c];
        vals[i] = x;
        s += x;
        sq += x * x;
    }
    float ws = warp_sum(s), wq = warp_sum(sq);
    int wid = tid >> 5, lane = tid & 31;
    if (lane == 0) { rs[wid] = ws; rq[wid] = wq; }
    __syncthreads();
    if (tid == 0) {
        float ta = 0.0f, tb = 0.0f;
#pragma unroll
        for (int i = 0; i < 8; i++) { ta += rs[i]; tb += rq[i]; }
        tot[0] = ta; tot[1] = tb;
    }
    __syncthreads();
    float mean = tot[0] * (1.0f / DD);
    float var = tot[1] * (1.0f / DD) - mean * mean;
    float inv = rsqrtf(var + 1e-5f);
#pragma unroll
    for (int i = 0; i < 4; i++) {
        int c = tid + i * 256;
        float o = (vals[i] - mean) * inv * g[c] + beta[c];
        out[rb + c] = o;
        if (ot) ot[rb + kperm(c)] = tf32r(o);
    }
}

// ---------------------------------------------------------------------------
// Launch
// ---------------------------------------------------------------------------
extern "C" void kernel_launch(void* const* d_in, const int* in_sizes, int n_in,
                              void* d_out, int out_size) {
    const float* ff    = (const float*)d_in[0];
    const int*   fi    = (const int*)d_in[1];
    const float* w_qkv = (const float*)d_in[2];
    const float* b_qkv = (const float*)d_in[3];
    const float* w_out = (const float*)d_in[4];
    const float* b_out = (const float*)d_in[5];
    const float* w1    = (const float*)d_in[6];
    const float* b1    = (const float*)d_in[7];
    const float* w2    = (const float*)d_in[8];
    const float* b2    = (const float*)d_in[9];
    const float* g1    = (const float*)d_in[10];
    const float* bet1  = (const float*)d_in[11];
    const float* g2    = (const float*)d_in[12];
    const float* bet2  = (const float*)d_in[13];
    float* out         = (float*)d_out;

    float *px, *pxt, *pqkv, *paot, *pproj, *ph, *pht, *pf1t, *pf2;
    float *pwqkvt, *pwoutt, *pw1t, *pw2t;
    cudaGetSymbolAddress((void**)&px, g_x);
    cudaGetSymbolAddress((void**)&pxt, g_xt);
    cudaGetSymbolAddress((void**)&pqkv, g_qkv);
    cudaGetSymbolAddress((void**)&paot, g_aot);
    cudaGetSymbolAddress((void**)&pproj, g_proj);
    cudaGetSymbolAddress((void**)&ph, g_h);
    cudaGetSymbolAddress((void**)&pht, g_ht);
    cudaGetSymbolAddress((void**)&pf1t, g_f1t);
    cudaGetSymbolAddress((void**)&pf2, g_f2);
    cudaGetSymbolAddress((void**)&pwqkvt, g_wqkvt);
    cudaGetSymbolAddress((void**)&pwoutt, g_woutt);
    cudaGetSymbolAddress((void**)&pw1t, g_w1t);
    cudaGetSymbolAddress((void**)&pw2t, g_w2t);

    cudaFuncSetAttribute(gemm_tf32, cudaFuncAttributeMaxDynamicSharedMemorySize, TGSMEM);

    // weight prep (round + permute)
    round_perm_kernel<<<(D3 * DD / 4 + 255) / 256, 256>>>(w_qkv, pwqkvt, D3 * DD / 4);
    round_perm_kernel<<<(DD * DD / 4 + 255) / 256, 256>>>(w_out, pwoutt, DD * DD / 4);
    round_perm_kernel<<<(D4 * DD / 4 + 255) / 256, 256>>>(w1, pw1t, D4 * DD / 4);
    round_perm_kernel<<<(DD * D4 / 4 + 255) / 256, 256>>>(w2, pw2t, DD * D4 / 4);

    // 1) PE add -> x (exact) + xt (tf32 perm)
    pe_add_kernel<<<(MTOK * DD / 2) / 256, 256>>>(ff, fi, px, pxt);

    // 2) QKV projection (tf32) -> fp32 qkv
    gemm_tf32<<<dim3(D3 / BN, MTOK / BM), 256, TGSMEM>>>(
        pxt, pwqkvt, b_qkv, pqkv, D3, DD, 0);

    // 3) windowed attention -> aot (tf32 perm)
    attn_win_kernel<<<dim3(HH, NWIN, BB), 256>>>(pqkv, paot);

    // 4) out projection (tf32) -> fp32 proj
    gemm_tf32<<<dim3(DD / BN, MTOK / BM), 256, TGSMEM>>>(
        paot, pwoutt, b_out, pproj, DD, DD, 0);

    // 5) LN1(x + proj) -> h (exact) + ht (tf32 perm)
    ln_add_kernel<<<MTOK, 256>>>(px, pproj, g1, bet1, ph, pht);

    // 6) FFN1 + GELU (tf32) -> f1t (tf32 perm)
    gemm_tf32<<<dim3(D4 / BN, MTOK / BM), 256, TGSMEM>>>(
        pht, pw1t, b1, pf1t, D4, DD, 1);

    // 7) FFN2 (tf32) -> f2 fp32
    gemm_tf32<<<dim3(DD / BN, MTOK / BM), 256, TGSMEM>>>(
        pf1t, pw2t, b2, pf2, DD, D4, 0);

    // 8) LN2(h + f2) -> out
    ln_add_kernel<<<MTOK, 256>>>(ph, pf2, g2, bet2, out, nullptr);
}